// round 5
// baseline (speedup 1.0000x reference)
#include <cuda_runtime.h>
#include <math.h>
#include <stdint.h>

#define BATCH   2
#define SEQL    2048
#define DEMB    2048
#define NHEADS  16
#define DHEAD   128
#define NTOK    (BATCH * SEQL)       // 4096
#define D3      (3 * DEMB)           // 6144

// combined score scale: log2(e)/sqrt(128), folded into Q at GEMM1 epilogue
#define QSC 0.1275174446f
#define NEGINF __int_as_float(0xff800000)

typedef unsigned long long ull;

// -------- scratch (__device__ globals; no allocs allowed) --------
__device__ float g_qkv [(size_t)NTOK * D3];     // 96 MB (tf32, Q pre-scaled)
__device__ float g_attn[(size_t)NTOK * DEMB];   // 32 MB (tf32-rounded)
__device__ float g_xtf [(size_t)NTOK * DEMB];   // 32 MB (tf32-rounded x)
__device__ float g_wT1 [(size_t)D3   * DEMB];   // 48 MB (w_in^T, tf32)
__device__ float g_wT2 [(size_t)DEMB * DEMB];   // 16 MB (w_out^T, tf32)

// ---------------- helpers ----------------
__device__ __forceinline__ uint32_t smem_u32(const void* p) {
    uint32_t a;
    asm("{ .reg .u64 t; cvta.to.shared.u64 t, %1; cvt.u32.u64 %0, t; }" : "=r"(a) : "l"(p));
    return a;
}
__device__ __forceinline__ float tf32r(float f) {
    uint32_t u = __float_as_uint(f);
    asm("cvt.rna.tf32.f32 %0, %0;" : "+r"(u));
    return __uint_as_float(u);
}
__device__ __forceinline__ float ex2(float x) {
    float y; asm("ex2.approx.f32 %0, %1;" : "=f"(y) : "f"(x)); return y;
}
__device__ __forceinline__ void cp_async16(uint32_t dst, const void* src) {
    asm volatile("cp.async.cg.shared.global [%0], [%1], 16;" :: "r"(dst), "l"(src) : "memory");
}
#define CP_COMMIT() asm volatile("cp.async.commit_group;" ::: "memory")
#define CP_WAIT(n)  asm volatile("cp.async.wait_group %0;" :: "n"(n) : "memory")

__device__ __forceinline__ void mma_tf32(float* c, const uint32_t* a, const uint32_t* b) {
    asm volatile(
        "mma.sync.aligned.m16n8k8.row.col.f32.tf32.tf32.f32 "
        "{%0,%1,%2,%3}, {%4,%5,%6,%7}, {%8,%9}, {%0,%1,%2,%3};"
        : "+f"(c[0]), "+f"(c[1]), "+f"(c[2]), "+f"(c[3])
        : "r"(a[0]), "r"(a[1]), "r"(a[2]), "r"(a[3]), "r"(b[0]), "r"(b[1]));
}

// ================================================================
// Prep kernels: tf32-round inputs, transpose weights to [N][K]
// ================================================================
__global__ void transpose_tf32_kernel(const float* __restrict__ src, float* __restrict__ dst,
                                      int R, int C) {
    __shared__ float tile[32][33];
    int bx = blockIdx.x * 32, by = blockIdx.y * 32;
    int x = bx + threadIdx.x;
    for (int i = threadIdx.y; i < 32; i += 8)
        tile[i][threadIdx.x] = src[(size_t)(by + i) * C + x];
    __syncthreads();
    int ox = by + threadIdx.x;
    for (int i = threadIdx.y; i < 32; i += 8)
        dst[(size_t)(bx + i) * R + ox] = tf32r(tile[threadIdx.x][i]);
}

__global__ void conv_tf32_kernel(const float* __restrict__ src, float* __restrict__ dst, int n4) {
    int i = blockIdx.x * blockDim.x + threadIdx.x;
    if (i < n4) {
        float4 v = ((const float4*)src)[i];
        v.x = tf32r(v.x); v.y = tf32r(v.y); v.z = tf32r(v.z); v.w = tf32r(v.w);
        ((float4*)dst)[i] = v;
    }
}

// ================================================================
// tf32 mma.sync GEMM: C[M,N] = A[M,K] @ Bt[N,K]^T + bias[N]
// CTA 128x256, 8 warps (warp tile 64x64), K-chunk 32, 3-stage cp.async,
// one __syncthreads per chunk. M%128==0, N%256==0, K%32==0.
// Epilogue: cols < qcols get *= QSC; round_out -> tf32r.
// ================================================================
#define LDT 36
#define STG_F ((128 + 256) * LDT)                       // floats per stage
#define GEMM_SMEM (3 * STG_F * (int)sizeof(float))      // 165888 B

__global__ __launch_bounds__(256, 1) void tf32_mma_gemm_kernel(
    const float* __restrict__ A, const float* __restrict__ Bt,
    const float* __restrict__ bias, float* __restrict__ C,
    int M, int N, int K, int qcols, int round_out)
{
    extern __shared__ float sm[];
    const int tid  = threadIdx.x;
    const int lane = tid & 31;
    const int wid  = tid >> 5;
    const int wm = wid >> 2;           // 0..1  -> 64-row slab
    const int wn = wid & 3;            // 0..3  -> 64-col slab
    const int g = lane >> 2, t = lane & 3;
    const int bm = blockIdx.x * 128;
    const int bn = blockIdx.y * 256;
    const int nchunks = K >> 5;

    float acc[4][8][4];
    #pragma unroll
    for (int mi = 0; mi < 4; mi++)
        #pragma unroll
        for (int ni = 0; ni < 8; ni++)
            #pragma unroll
            for (int q = 0; q < 4; q++) acc[mi][ni][q] = 0.0f;

    // ---- stage loader: A 128x32 (4 cp/thread), B 256x32 (8 cp/thread) ----
    auto load_stage = [&](int c, int p) {
        const int kb = c << 5;
        float* dstA = sm + p * STG_F;
        float* dstB = dstA + 128 * LDT;
        const int row = tid >> 3;               // 0..31 step handled below
        const int c4  = (tid & 7) << 2;
        #pragma unroll
        for (int i = 0; i < 4; i++) {
            int r = row + i * 32;               // 0..127
            cp_async16(smem_u32(dstA + r * LDT + c4),
                       A + (size_t)(bm + r) * K + kb + c4);
        }
        #pragma unroll
        for (int i = 0; i < 8; i++) {
            int r = row + i * 32;               // 0..255
            cp_async16(smem_u32(dstB + r * LDT + c4),
                       Bt + (size_t)(bn + r) * K + kb + c4);
        }
        CP_COMMIT();
    };

    load_stage(0, 0);
    if (nchunks > 1) load_stage(1, 1);

    for (int c = 0; c < nchunks; c++) {
        if (c + 1 < nchunks) { CP_WAIT(1); } else { CP_WAIT(0); }
        __syncthreads();                         // stage c visible; c-1 compute done

        if (c + 2 < nchunks) load_stage(c + 2, (c + 2) % 3);

        const float* sA = sm + (c % 3) * STG_F;
        const float* sB = sA + 128 * LDT;
        #pragma unroll
        for (int ks = 0; ks < 4; ks++) {
            const int kb = ks * 8;
            uint32_t af[4][4], bf[8][2];
            #pragma unroll
            for (int mi = 0; mi < 4; mi++) {
                const float* base = sA + (wm * 64 + mi * 16 + g) * LDT + kb + t;
                af[mi][0] = __float_as_uint(base[0]);
                af[mi][1] = __float_as_uint(base[8 * LDT]);
                af[mi][2] = __float_as_uint(base[4]);
                af[mi][3] = __float_as_uint(base[8 * LDT + 4]);
            }
            #pragma unroll
            for (int ni = 0; ni < 8; ni++) {
                const float* base = sB + (wn * 64 + ni * 8 + g) * LDT + kb + t;
                bf[ni][0] = __float_as_uint(base[0]);
                bf[ni][1] = __float_as_uint(base[4]);
            }
            #pragma unroll
            for (int mi = 0; mi < 4; mi++)
                #pragma unroll
                for (int ni = 0; ni < 8; ni++)
                    mma_tf32(acc[mi][ni], af[mi], bf[ni]);
        }
    }
    __syncthreads();

    // ---- epilogue ----
    #pragma unroll
    for (int mi = 0; mi < 4; mi++) {
        const int r0 = bm + wm * 64 + mi * 16 + g;
        #pragma unroll
        for (int ni = 0; ni < 8; ni++) {
            const int n = bn + wn * 64 + ni * 8 + t * 2;
            const float sc = (n < qcols) ? QSC : 1.0f;
            float2 bv = *(const float2*)(bias + n);
            float v0 = (acc[mi][ni][0] + bv.x) * sc;
            float v1 = (acc[mi][ni][1] + bv.y) * sc;
            float v2 = (acc[mi][ni][2] + bv.x) * sc;
            float v3 = (acc[mi][ni][3] + bv.y) * sc;
            if (round_out) { v0 = tf32r(v0); v1 = tf32r(v1); v2 = tf32r(v2); v3 = tf32r(v3); }
            *(float2*)(C + (size_t)r0 * N + n)       = make_float2(v0, v1);
            *(float2*)(C + (size_t)(r0 + 8) * N + n) = make_float2(v2, v3);
        }
    }
}

// ================================================================
// Flash attention on mma.sync tf32 (unchanged from R4 — matched model).
// ================================================================
#define LDP 132
#define FL_K  (128 * LDP)
#define FL_V  (2 * 128 * LDP)
#define FL_RM (3 * 128 * LDP)
#define FL_RS (FL_RM + 512)
#define FLASH_SMEM ((FL_RS + 512) * (int)sizeof(float))   // 206848 B

__global__ __launch_bounds__(256, 1) void flash_mma_kernel(
    const float* __restrict__ qkv, float* __restrict__ attn_out)
{
    extern __shared__ float sm[];
    float* Qs    = sm;
    float* KPs   = sm + FL_K;
    float* Vs    = sm + FL_V;
    float* red_m = sm + FL_RM;
    float* red_s = sm + FL_RS;

    const int qt  = (int)gridDim.x - 1 - (int)blockIdx.x;   // heavy first
    const int h   = blockIdx.y;
    const int b   = blockIdx.z;
    const int tid  = threadIdx.x;
    const int lane = tid & 31;
    const int wid  = tid >> 5;
    const int wm = wid >> 2, wn = wid & 3;
    const int g = lane >> 2, t = lane & 3;

    const float* qbase = qkv + (size_t)(b * SEQL + qt * 128) * D3 + h * DHEAD;
    #pragma unroll
    for (int i = 0; i < 16; i++) {
        int idx = tid + i * 256;
        int r  = idx >> 5;
        int c4 = (idx & 31) * 4;
        cp_async16(smem_u32(Qs + r * LDP + c4), qbase + (size_t)r * D3 + c4);
    }
    CP_COMMIT();

    float o[4][4][4];
    #pragma unroll
    for (int mi = 0; mi < 4; mi++)
        #pragma unroll
        for (int ni = 0; ni < 4; ni++)
            #pragma unroll
            for (int q = 0; q < 4; q++) o[mi][ni][q] = 0.0f;
    float mrow[4][2], lrow[4][2];
    #pragma unroll
    for (int mi = 0; mi < 4; mi++) {
        mrow[mi][0] = NEGINF; mrow[mi][1] = NEGINF;
        lrow[mi][0] = 0.0f;   lrow[mi][1] = 0.0f;
    }

    for (int jt = 0; jt <= qt; jt++) {
        const float* kbase = qkv + (size_t)(b * SEQL + jt * 128) * D3 + DEMB + h * DHEAD;
        #pragma unroll
        for (int i = 0; i < 16; i++) {
            int idx = tid + i * 256;
            int r  = idx >> 5;
            int c4 = (idx & 31) * 4;
            cp_async16(smem_u32(KPs + r * LDP + c4), kbase + (size_t)r * D3 + c4);
        }
        CP_COMMIT();
        #pragma unroll
        for (int i = 0; i < 16; i++) {
            int idx = tid + i * 256;
            int r  = idx >> 5;
            int c4 = (idx & 31) * 4;
            cp_async16(smem_u32(Vs + r * LDP + c4), kbase + DEMB + (size_t)r * D3 + c4);
        }
        CP_COMMIT();
        CP_WAIT(1);
        __syncthreads();

        float s[4][4][4];
        #pragma unroll
        for (int mi = 0; mi < 4; mi++)
            #pragma unroll
            for (int ni = 0; ni < 4; ni++)
                #pragma unroll
                for (int q = 0; q < 4; q++) s[mi][ni][q] = 0.0f;

        #pragma unroll
        for (int ks = 0; ks < 16; ks++) {
            const int kb = ks * 8;
            uint32_t af[4][4], bf[4][2];
            #pragma unroll
            for (int mi = 0; mi < 4; mi++) {
                const float* base = Qs + (wm * 64 + mi * 16 + g) * LDP + kb + t;
                af[mi][0] = __float_as_uint(base[0]);
                af[mi][1] = __float_as_uint(base[8 * LDP]);
                af[mi][2] = __float_as_uint(base[4]);
                af[mi][3] = __float_as_uint(base[8 * LDP + 4]);
            }
            #pragma unroll
            for (int ni = 0; ni < 4; ni++) {
                const float* base = KPs + (wn * 32 + ni * 8 + g) * LDP + kb + t;
                bf[ni][0] = __float_as_uint(base[0]);
                bf[ni][1] = __float_as_uint(base[4]);
            }
            #pragma unroll
            for (int mi = 0; mi < 4; mi++)
                #pragma unroll
                for (int ni = 0; ni < 4; ni++)
                    mma_tf32(s[mi][ni], af[mi], bf[ni]);
        }

        if (jt == qt) {
            #pragma unroll
            for (int mi = 0; mi < 4; mi++) {
                const int r0 = wm * 64 + mi * 16 + g;
                #pragma unroll
                for (int ni = 0; ni < 4; ni++) {
                    const int c = wn * 32 + ni * 8 + 2 * t;
                    if (c     > r0)     s[mi][ni][0] = NEGINF;
                    if (c + 1 > r0)     s[mi][ni][1] = NEGINF;
                    if (c     > r0 + 8) s[mi][ni][2] = NEGINF;
                    if (c + 1 > r0 + 8) s[mi][ni][3] = NEGINF;
                }
            }
        }

        float mt[4][2];
        #pragma unroll
        for (int mi = 0; mi < 4; mi++) {
            float a = fmaxf(s[mi][0][0], s[mi][0][1]);
            float bq = fmaxf(s[mi][0][2], s[mi][0][3]);
            #pragma unroll
            for (int ni = 1; ni < 4; ni++) {
                a  = fmaxf(a,  fmaxf(s[mi][ni][0], s[mi][ni][1]));
                bq = fmaxf(bq, fmaxf(s[mi][ni][2], s[mi][ni][3]));
            }
            mt[mi][0] = a; mt[mi][1] = bq;
        }
        #pragma unroll
        for (int off = 1; off <= 2; off <<= 1) {
            #pragma unroll
            for (int mi = 0; mi < 4; mi++) {
                mt[mi][0] = fmaxf(mt[mi][0], __shfl_xor_sync(0xffffffffu, mt[mi][0], off));
                mt[mi][1] = fmaxf(mt[mi][1], __shfl_xor_sync(0xffffffffu, mt[mi][1], off));
            }
        }
        if (t == 0) {
            #pragma unroll
            for (int mi = 0; mi < 4; mi++) {
                red_m[wn * 128 + wm * 64 + mi * 16 + g]     = mt[mi][0];
                red_m[wn * 128 + wm * 64 + mi * 16 + g + 8] = mt[mi][1];
            }
        }
        __syncthreads();

        float mnew[4][2], fsc[4][2];
        #pragma unroll
        for (int mi = 0; mi < 4; mi++) {
            #pragma unroll
            for (int hh = 0; hh < 2; hh++) {
                const int row = wm * 64 + mi * 16 + g + 8 * hh;
                float v = fmaxf(fmaxf(red_m[row], red_m[128 + row]),
                                fmaxf(red_m[256 + row], red_m[384 + row]));
                float mn = fmaxf(mrow[mi][hh], v);
                fsc[mi][hh]  = ex2(mrow[mi][hh] - mn);
                mnew[mi][hh] = mn;
                mrow[mi][hh] = mn;
            }
        }

        float rs[4][2];
        #pragma unroll
        for (int mi = 0; mi < 4; mi++) { rs[mi][0] = 0.0f; rs[mi][1] = 0.0f; }
        #pragma unroll
        for (int mi = 0; mi < 4; mi++) {
            #pragma unroll
            for (int ni = 0; ni < 4; ni++) {
                s[mi][ni][0] = ex2(s[mi][ni][0] - mnew[mi][0]);
                s[mi][ni][1] = ex2(s[mi][ni][1] - mnew[mi][0]);
                s[mi][ni][2] = ex2(s[mi][ni][2] - mnew[mi][1]);
                s[mi][ni][3] = ex2(s[mi][ni][3] - mnew[mi][1]);
                rs[mi][0] += s[mi][ni][0] + s[mi][ni][1];
                rs[mi][1] += s[mi][ni][2] + s[mi][ni][3];
            }
        }
        #pragma unroll
        for (int off = 1; off <= 2; off <<= 1) {
            #pragma unroll
            for (int mi = 0; mi < 4; mi++) {
                rs[mi][0] += __shfl_xor_sync(0xffffffffu, rs[mi][0], off);
                rs[mi][1] += __shfl_xor_sync(0xffffffffu, rs[mi][1], off);
            }
        }
        if (t == 0) {
            #pragma unroll
            for (int mi = 0; mi < 4; mi++) {
                red_s[wn * 128 + wm * 64 + mi * 16 + g]     = rs[mi][0];
                red_s[wn * 128 + wm * 64 + mi * 16 + g + 8] = rs[mi][1];
            }
        }

        #pragma unroll
        for (int mi = 0; mi < 4; mi++) {
            const int r0 = wm * 64 + mi * 16 + g;
            #pragma unroll
            for (int ni = 0; ni < 4; ni++) {
                const int c = wn * 32 + ni * 8 + 2 * t;
                *(float2*)&KPs[r0 * LDP + c] =
                    make_float2(tf32r(s[mi][ni][0]), tf32r(s[mi][ni][1]));
                *(float2*)&KPs[(r0 + 8) * LDP + c] =
                    make_float2(tf32r(s[mi][ni][2]), tf32r(s[mi][ni][3]));
            }
        }
        CP_WAIT(0);
        __syncthreads();

        #pragma unroll
        for (int mi = 0; mi < 4; mi++) {
            #pragma unroll
            for (int hh = 0; hh < 2; hh++) {
                const int row = wm * 64 + mi * 16 + g + 8 * hh;
                float sum = red_s[row] + red_s[128 + row] + red_s[256 + row] + red_s[384 + row];
                lrow[mi][hh] = lrow[mi][hh] * fsc[mi][hh] + sum;
            }
            #pragma unroll
            for (int ni = 0; ni < 4; ni++) {
                o[mi][ni][0] *= fsc[mi][0];
                o[mi][ni][1] *= fsc[mi][0];
                o[mi][ni][2] *= fsc[mi][1];
                o[mi][ni][3] *= fsc[mi][1];
            }
        }

        #pragma unroll
        for (int ks = 0; ks < 16; ks++) {
            const int kb = ks * 8;
            uint32_t af[4][4], bf[4][2];
            #pragma unroll
            for (int mi = 0; mi < 4; mi++) {
                const float* base = KPs + (wm * 64 + mi * 16 + g) * LDP + kb + t;
                af[mi][0] = __float_as_uint(base[0]);
                af[mi][1] = __float_as_uint(base[8 * LDP]);
                af[mi][2] = __float_as_uint(base[4]);
                af[mi][3] = __float_as_uint(base[8 * LDP + 4]);
            }
            #pragma unroll
            for (int ni = 0; ni < 4; ni++) {
                const int n = wn * 32 + ni * 8 + g;
                bf[ni][0] = __float_as_uint(Vs[(kb + t) * LDP + n]);
                bf[ni][1] = __float_as_uint(Vs[(kb + t + 4) * LDP + n]);
            }
            #pragma unroll
            for (int mi = 0; mi < 4; mi++)
                #pragma unroll
                for (int ni = 0; ni < 4; ni++)
                    mma_tf32(o[mi][ni], af[mi], bf[ni]);
        }
        __syncthreads();
    }

    const size_t orow = (size_t)(b * SEQL + qt * 128);
    #pragma unroll
    for (int mi = 0; mi < 4; mi++) {
        const float i0 = 1.0f / lrow[mi][0];
        const float i1 = 1.0f / lrow[mi][1];
        const int r0 = wm * 64 + mi * 16 + g;
        #pragma unroll
        for (int ni = 0; ni < 4; ni++) {
            const int cc = h * DHEAD + wn * 32 + ni * 8 + 2 * t;
            *(float2*)(attn_out + (orow + r0) * DEMB + cc) =
                make_float2(tf32r(o[mi][ni][0] * i0), tf32r(o[mi][ni][1] * i0));
            *(float2*)(attn_out + (orow + r0 + 8) * DEMB + cc) =
                make_float2(tf32r(o[mi][ni][2] * i1), tf32r(o[mi][ni][3] * i1));
        }
    }
}

// ================================================================
// Launcher
// ================================================================
extern "C" void kernel_launch(void* const* d_in, const int* in_sizes, int n_in,
                              void* d_out, int out_size)
{
    (void)in_sizes; (void)n_in; (void)out_size;
    const float* x     = (const float*)d_in[0];
    const float* w_in  = (const float*)d_in[1];
    const float* b_in  = (const float*)d_in[2];
    const float* w_out = (const float*)d_in[3];
    const float* b_out = (const float*)d_in[4];
    float* out = (float*)d_out;

    void *qkv_p, *attn_p, *xtf_p, *wT1_p, *wT2_p;
    cudaGetSymbolAddress(&qkv_p,  g_qkv);
    cudaGetSymbolAddress(&attn_p, g_attn);
    cudaGetSymbolAddress(&xtf_p,  g_xtf);
    cudaGetSymbolAddress(&wT1_p,  g_wT1);
    cudaGetSymbolAddress(&wT2_p,  g_wT2);

    cudaFuncSetAttribute(flash_mma_kernel,
                         cudaFuncAttributeMaxDynamicSharedMemorySize, FLASH_SMEM);
    cudaFuncSetAttribute(tf32_mma_gemm_kernel,
                         cudaFuncAttributeMaxDynamicSharedMemorySize, GEMM_SMEM);

    // prep: wT1 = tf32(w_in^T), wT2 = tf32(w_out^T), xtf = tf32(x)
    transpose_tf32_kernel<<<dim3(D3 / 32, DEMB / 32), dim3(32, 8)>>>(w_in, (float*)wT1_p, DEMB, D3);
    transpose_tf32_kernel<<<dim3(DEMB / 32, DEMB / 32), dim3(32, 8)>>>(w_out, (float*)wT2_p, DEMB, DEMB);
    conv_tf32_kernel<<<(NTOK * DEMB / 4 + 255) / 256, 256>>>(x, (float*)xtf_p, NTOK * DEMB / 4);

    // 1) qkv = x @ w_in + b_in  (tf32-rounded out; Q cols pre-scaled by QSC)
    tf32_mma_gemm_kernel<<<dim3(NTOK / 128, D3 / 256), 256, GEMM_SMEM>>>(
        (const float*)xtf_p, (const float*)wT1_p, b_in, (float*)qkv_p,
        NTOK, D3, DEMB, DEMB, 1);

    // 2) causal flash attention (mma.sync tf32) -> g_attn (tf32-rounded)
    flash_mma_kernel<<<dim3(SEQL / 128, NHEADS, BATCH), 256, FLASH_SMEM>>>(
        (const float*)qkv_p, (float*)attn_p);

    // 3) out = attn @ w_out + b_out  (full fp32 out)
    tf32_mma_gemm_kernel<<<dim3(NTOK / 128, DEMB / 256), 256, GEMM_SMEM>>>(
        (const float*)attn_p, (const float*)wT2_p, b_out, out,
        NTOK, DEMB, DEMB, 0, 0);
}

// round 6
// speedup vs baseline: 1.0692x; 1.0692x over previous
#include <cuda_runtime.h>
#include <math.h>
#include <stdint.h>

#define BATCH   2
#define SEQL    2048
#define DEMB    2048
#define NHEADS  16
#define DHEAD   128
#define NTOK    (BATCH * SEQL)       // 4096
#define D3      (3 * DEMB)           // 6144

// combined score scale: log2(e)/sqrt(128), folded into Q at GEMM1 epilogue
#define QSC 0.1275174446f
#define NEGINF __int_as_float(0xff800000)

typedef unsigned long long ull;

// -------- scratch (__device__ globals; no allocs allowed) --------
__device__ float g_qkv [(size_t)NTOK * D3];     // 96 MB (tf32, Q pre-scaled)
__device__ float g_attn[(size_t)NTOK * DEMB];   // 32 MB (tf32-rounded)
__device__ float g_xtf [(size_t)NTOK * DEMB];   // 32 MB (tf32-rounded x)
__device__ float g_wT1 [(size_t)D3   * DEMB];   // 48 MB (w_in^T, tf32)
__device__ float g_wT2 [(size_t)DEMB * DEMB];   // 16 MB (w_out^T, tf32)

// ---------------- helpers ----------------
__device__ __forceinline__ uint32_t smem_u32(const void* p) {
    uint32_t a;
    asm("{ .reg .u64 t; cvta.to.shared.u64 t, %1; cvt.u32.u64 %0, t; }" : "=r"(a) : "l"(p));
    return a;
}
__device__ __forceinline__ float tf32r(float f) {
    uint32_t u = __float_as_uint(f);
    asm("cvt.rna.tf32.f32 %0, %0;" : "+r"(u));
    return __uint_as_float(u);
}
__device__ __forceinline__ float ex2(float x) {
    float y; asm("ex2.approx.f32 %0, %1;" : "=f"(y) : "f"(x)); return y;
}
__device__ __forceinline__ void cp_async16(uint32_t dst, const void* src) {
    asm volatile("cp.async.cg.shared.global [%0], [%1], 16;" :: "r"(dst), "l"(src) : "memory");
}
#define CP_COMMIT() asm volatile("cp.async.commit_group;" ::: "memory")
#define CP_WAIT(n)  asm volatile("cp.async.wait_group %0;" :: "n"(n) : "memory")

__device__ __forceinline__ void mma_tf32(float* c, const uint32_t* a, const uint32_t* b) {
    asm volatile(
        "mma.sync.aligned.m16n8k8.row.col.f32.tf32.tf32.f32 "
        "{%0,%1,%2,%3}, {%4,%5,%6,%7}, {%8,%9}, {%0,%1,%2,%3};"
        : "+f"(c[0]), "+f"(c[1]), "+f"(c[2]), "+f"(c[3])
        : "r"(a[0]), "r"(a[1]), "r"(a[2]), "r"(a[3]), "r"(b[0]), "r"(b[1]));
}

// ================================================================
// Prep kernels: tf32-round inputs, transpose weights to [N][K]
// ================================================================
__global__ void transpose_tf32_kernel(const float* __restrict__ src, float* __restrict__ dst,
                                      int R, int C) {
    __shared__ float tile[32][33];
    int bx = blockIdx.x * 32, by = blockIdx.y * 32;
    int x = bx + threadIdx.x;
    for (int i = threadIdx.y; i < 32; i += 8)
        tile[i][threadIdx.x] = src[(size_t)(by + i) * C + x];
    __syncthreads();
    int ox = by + threadIdx.x;
    for (int i = threadIdx.y; i < 32; i += 8)
        dst[(size_t)(bx + i) * R + ox] = tf32r(tile[threadIdx.x][i]);
}

__global__ void conv_tf32_kernel(const float* __restrict__ src, float* __restrict__ dst, int n4) {
    int i = blockIdx.x * blockDim.x + threadIdx.x;
    if (i < n4) {
        float4 v = ((const float4*)src)[i];
        v.x = tf32r(v.x); v.y = tf32r(v.y); v.z = tf32r(v.z); v.w = tf32r(v.w);
        ((float4*)dst)[i] = v;
    }
}

// ================================================================
// tf32 mma.sync GEMM: C[M,N] = A[M,K] @ Bt[N,K]^T + bias[N]
// CTA 128x128, 8 warps (warp tile 64x32), K-chunk 32, 3-stage cp.async,
// ONE __syncthreads per chunk. 2 CTAs/SM. M%128==0, N%128==0, K%32==0.
// Epilogue: cols < qcols get *= QSC; round_out -> tf32r.
// ================================================================
#define LDT 36
#define STG_F (2 * 128 * LDT)                            // floats per stage
#define GEMM_SMEM (3 * STG_F * (int)sizeof(float))       // 110592 B

__global__ __launch_bounds__(256, 2) void tf32_mma_gemm_kernel(
    const float* __restrict__ A, const float* __restrict__ Bt,
    const float* __restrict__ bias, float* __restrict__ C,
    int M, int N, int K, int qcols, int round_out)
{
    extern __shared__ float sm[];
    const int tid  = threadIdx.x;
    const int lane = tid & 31;
    const int wid  = tid >> 5;
    const int wm = wid >> 2;           // 0..1  -> 64-row slab
    const int wn = wid & 3;            // 0..3  -> 32-col slab
    const int g = lane >> 2, t = lane & 3;
    const int bm = blockIdx.x * 128;
    const int bn = blockIdx.y * 128;
    const int nchunks = K >> 5;

    float acc[4][4][4];
    #pragma unroll
    for (int mi = 0; mi < 4; mi++)
        #pragma unroll
        for (int ni = 0; ni < 4; ni++)
            #pragma unroll
            for (int q = 0; q < 4; q++) acc[mi][ni][q] = 0.0f;

    auto load_stage = [&](int c, int p) {
        const int kb = c << 5;
        float* dstA = sm + p * STG_F;
        float* dstB = dstA + 128 * LDT;
        const int row = tid >> 3;               // 0..31
        const int c4  = (tid & 7) << 2;         // 0..28
        #pragma unroll
        for (int i = 0; i < 4; i++) {
            int r = row + i * 32;               // 0..127
            cp_async16(smem_u32(dstA + r * LDT + c4),
                       A + (size_t)(bm + r) * K + kb + c4);
            cp_async16(smem_u32(dstB + r * LDT + c4),
                       Bt + (size_t)(bn + r) * K + kb + c4);
        }
        CP_COMMIT();
    };

    load_stage(0, 0);
    if (nchunks > 1) load_stage(1, 1);

    for (int c = 0; c < nchunks; c++) {
        if (c + 1 < nchunks) { CP_WAIT(1); } else { CP_WAIT(0); }
        __syncthreads();                // stage c visible; compute c-1 done everywhere

        if (c + 2 < nchunks) load_stage(c + 2, (c + 2) % 3);

        const float* sA = sm + (c % 3) * STG_F;
        const float* sB = sA + 128 * LDT;
        #pragma unroll
        for (int ks = 0; ks < 4; ks++) {
            const int kb = ks * 8;
            uint32_t af[4][4], bf[4][2];
            #pragma unroll
            for (int mi = 0; mi < 4; mi++) {
                const float* base = sA + (wm * 64 + mi * 16 + g) * LDT + kb + t;
                af[mi][0] = __float_as_uint(base[0]);
                af[mi][1] = __float_as_uint(base[8 * LDT]);
                af[mi][2] = __float_as_uint(base[4]);
                af[mi][3] = __float_as_uint(base[8 * LDT + 4]);
            }
            #pragma unroll
            for (int ni = 0; ni < 4; ni++) {
                const float* base = sB + (wn * 32 + ni * 8 + g) * LDT + kb + t;
                bf[ni][0] = __float_as_uint(base[0]);
                bf[ni][1] = __float_as_uint(base[4]);
            }
            #pragma unroll
            for (int mi = 0; mi < 4; mi++)
                #pragma unroll
                for (int ni = 0; ni < 4; ni++)
                    mma_tf32(acc[mi][ni], af[mi], bf[ni]);
        }
    }
    __syncthreads();

    // ---- epilogue ----
    #pragma unroll
    for (int mi = 0; mi < 4; mi++) {
        const int r0 = bm + wm * 64 + mi * 16 + g;
        #pragma unroll
        for (int ni = 0; ni < 4; ni++) {
            const int n = bn + wn * 32 + ni * 8 + t * 2;
            const float sc = (n < qcols) ? QSC : 1.0f;
            float2 bv = *(const float2*)(bias + n);
            float v0 = (acc[mi][ni][0] + bv.x) * sc;
            float v1 = (acc[mi][ni][1] + bv.y) * sc;
            float v2 = (acc[mi][ni][2] + bv.x) * sc;
            float v3 = (acc[mi][ni][3] + bv.y) * sc;
            if (round_out) { v0 = tf32r(v0); v1 = tf32r(v1); v2 = tf32r(v2); v3 = tf32r(v3); }
            *(float2*)(C + (size_t)r0 * N + n)       = make_float2(v0, v1);
            *(float2*)(C + (size_t)(r0 + 8) * N + n) = make_float2(v2, v3);
        }
    }
}

// ================================================================
// Flash attention on mma.sync tf32 (unchanged from R4 — matched model).
// ================================================================
#define LDP 132
#define FL_K  (128 * LDP)
#define FL_V  (2 * 128 * LDP)
#define FL_RM (3 * 128 * LDP)
#define FL_RS (FL_RM + 512)
#define FLASH_SMEM ((FL_RS + 512) * (int)sizeof(float))   // 206848 B

__global__ __launch_bounds__(256, 1) void flash_mma_kernel(
    const float* __restrict__ qkv, float* __restrict__ attn_out)
{
    extern __shared__ float sm[];
    float* Qs    = sm;
    float* KPs   = sm + FL_K;
    float* Vs    = sm + FL_V;
    float* red_m = sm + FL_RM;
    float* red_s = sm + FL_RS;

    const int qt  = (int)gridDim.x - 1 - (int)blockIdx.x;   // heavy first
    const int h   = blockIdx.y;
    const int b   = blockIdx.z;
    const int tid  = threadIdx.x;
    const int lane = tid & 31;
    const int wid  = tid >> 5;
    const int wm = wid >> 2, wn = wid & 3;
    const int g = lane >> 2, t = lane & 3;

    const float* qbase = qkv + (size_t)(b * SEQL + qt * 128) * D3 + h * DHEAD;
    #pragma unroll
    for (int i = 0; i < 16; i++) {
        int idx = tid + i * 256;
        int r  = idx >> 5;
        int c4 = (idx & 31) * 4;
        cp_async16(smem_u32(Qs + r * LDP + c4), qbase + (size_t)r * D3 + c4);
    }
    CP_COMMIT();

    float o[4][4][4];
    #pragma unroll
    for (int mi = 0; mi < 4; mi++)
        #pragma unroll
        for (int ni = 0; ni < 4; ni++)
            #pragma unroll
            for (int q = 0; q < 4; q++) o[mi][ni][q] = 0.0f;
    float mrow[4][2], lrow[4][2];
    #pragma unroll
    for (int mi = 0; mi < 4; mi++) {
        mrow[mi][0] = NEGINF; mrow[mi][1] = NEGINF;
        lrow[mi][0] = 0.0f;   lrow[mi][1] = 0.0f;
    }

    for (int jt = 0; jt <= qt; jt++) {
        const float* kbase = qkv + (size_t)(b * SEQL + jt * 128) * D3 + DEMB + h * DHEAD;
        #pragma unroll
        for (int i = 0; i < 16; i++) {
            int idx = tid + i * 256;
            int r  = idx >> 5;
            int c4 = (idx & 31) * 4;
            cp_async16(smem_u32(KPs + r * LDP + c4), kbase + (size_t)r * D3 + c4);
        }
        CP_COMMIT();
        #pragma unroll
        for (int i = 0; i < 16; i++) {
            int idx = tid + i * 256;
            int r  = idx >> 5;
            int c4 = (idx & 31) * 4;
            cp_async16(smem_u32(Vs + r * LDP + c4), kbase + DEMB + (size_t)r * D3 + c4);
        }
        CP_COMMIT();
        CP_WAIT(1);
        __syncthreads();

        float s[4][4][4];
        #pragma unroll
        for (int mi = 0; mi < 4; mi++)
            #pragma unroll
            for (int ni = 0; ni < 4; ni++)
                #pragma unroll
                for (int q = 0; q < 4; q++) s[mi][ni][q] = 0.0f;

        #pragma unroll
        for (int ks = 0; ks < 16; ks++) {
            const int kb = ks * 8;
            uint32_t af[4][4], bf[4][2];
            #pragma unroll
            for (int mi = 0; mi < 4; mi++) {
                const float* base = Qs + (wm * 64 + mi * 16 + g) * LDP + kb + t;
                af[mi][0] = __float_as_uint(base[0]);
                af[mi][1] = __float_as_uint(base[8 * LDP]);
                af[mi][2] = __float_as_uint(base[4]);
                af[mi][3] = __float_as_uint(base[8 * LDP + 4]);
            }
            #pragma unroll
            for (int ni = 0; ni < 4; ni++) {
                const float* base = KPs + (wn * 32 + ni * 8 + g) * LDP + kb + t;
                bf[ni][0] = __float_as_uint(base[0]);
                bf[ni][1] = __float_as_uint(base[4]);
            }
            #pragma unroll
            for (int mi = 0; mi < 4; mi++)
                #pragma unroll
                for (int ni = 0; ni < 4; ni++)
                    mma_tf32(s[mi][ni], af[mi], bf[ni]);
        }

        if (jt == qt) {
            #pragma unroll
            for (int mi = 0; mi < 4; mi++) {
                const int r0 = wm * 64 + mi * 16 + g;
                #pragma unroll
                for (int ni = 0; ni < 4; ni++) {
                    const int c = wn * 32 + ni * 8 + 2 * t;
                    if (c     > r0)     s[mi][ni][0] = NEGINF;
                    if (c + 1 > r0)     s[mi][ni][1] = NEGINF;
                    if (c     > r0 + 8) s[mi][ni][2] = NEGINF;
                    if (c + 1 > r0 + 8) s[mi][ni][3] = NEGINF;
                }
            }
        }

        float mt[4][2];
        #pragma unroll
        for (int mi = 0; mi < 4; mi++) {
            float a = fmaxf(s[mi][0][0], s[mi][0][1]);
            float bq = fmaxf(s[mi][0][2], s[mi][0][3]);
            #pragma unroll
            for (int ni = 1; ni < 4; ni++) {
                a  = fmaxf(a,  fmaxf(s[mi][ni][0], s[mi][ni][1]));
                bq = fmaxf(bq, fmaxf(s[mi][ni][2], s[mi][ni][3]));
            }
            mt[mi][0] = a; mt[mi][1] = bq;
        }
        #pragma unroll
        for (int off = 1; off <= 2; off <<= 1) {
            #pragma unroll
            for (int mi = 0; mi < 4; mi++) {
                mt[mi][0] = fmaxf(mt[mi][0], __shfl_xor_sync(0xffffffffu, mt[mi][0], off));
                mt[mi][1] = fmaxf(mt[mi][1], __shfl_xor_sync(0xffffffffu, mt[mi][1], off));
            }
        }
        if (t == 0) {
            #pragma unroll
            for (int mi = 0; mi < 4; mi++) {
                red_m[wn * 128 + wm * 64 + mi * 16 + g]     = mt[mi][0];
                red_m[wn * 128 + wm * 64 + mi * 16 + g + 8] = mt[mi][1];
            }
        }
        __syncthreads();

        float mnew[4][2], fsc[4][2];
        #pragma unroll
        for (int mi = 0; mi < 4; mi++) {
            #pragma unroll
            for (int hh = 0; hh < 2; hh++) {
                const int row = wm * 64 + mi * 16 + g + 8 * hh;
                float v = fmaxf(fmaxf(red_m[row], red_m[128 + row]),
                                fmaxf(red_m[256 + row], red_m[384 + row]));
                float mn = fmaxf(mrow[mi][hh], v);
                fsc[mi][hh]  = ex2(mrow[mi][hh] - mn);
                mnew[mi][hh] = mn;
                mrow[mi][hh] = mn;
            }
        }

        float rs[4][2];
        #pragma unroll
        for (int mi = 0; mi < 4; mi++) { rs[mi][0] = 0.0f; rs[mi][1] = 0.0f; }
        #pragma unroll
        for (int mi = 0; mi < 4; mi++) {
            #pragma unroll
            for (int ni = 0; ni < 4; ni++) {
                s[mi][ni][0] = ex2(s[mi][ni][0] - mnew[mi][0]);
                s[mi][ni][1] = ex2(s[mi][ni][1] - mnew[mi][0]);
                s[mi][ni][2] = ex2(s[mi][ni][2] - mnew[mi][1]);
                s[mi][ni][3] = ex2(s[mi][ni][3] - mnew[mi][1]);
                rs[mi][0] += s[mi][ni][0] + s[mi][ni][1];
                rs[mi][1] += s[mi][ni][2] + s[mi][ni][3];
            }
        }
        #pragma unroll
        for (int off = 1; off <= 2; off <<= 1) {
            #pragma unroll
            for (int mi = 0; mi < 4; mi++) {
                rs[mi][0] += __shfl_xor_sync(0xffffffffu, rs[mi][0], off);
                rs[mi][1] += __shfl_xor_sync(0xffffffffu, rs[mi][1], off);
            }
        }
        if (t == 0) {
            #pragma unroll
            for (int mi = 0; mi < 4; mi++) {
                red_s[wn * 128 + wm * 64 + mi * 16 + g]     = rs[mi][0];
                red_s[wn * 128 + wm * 64 + mi * 16 + g + 8] = rs[mi][1];
            }
        }

        #pragma unroll
        for (int mi = 0; mi < 4; mi++) {
            const int r0 = wm * 64 + mi * 16 + g;
            #pragma unroll
            for (int ni = 0; ni < 4; ni++) {
                const int c = wn * 32 + ni * 8 + 2 * t;
                *(float2*)&KPs[r0 * LDP + c] =
                    make_float2(tf32r(s[mi][ni][0]), tf32r(s[mi][ni][1]));
                *(float2*)&KPs[(r0 + 8) * LDP + c] =
                    make_float2(tf32r(s[mi][ni][2]), tf32r(s[mi][ni][3]));
            }
        }
        CP_WAIT(0);
        __syncthreads();

        #pragma unroll
        for (int mi = 0; mi < 4; mi++) {
            #pragma unroll
            for (int hh = 0; hh < 2; hh++) {
                const int row = wm * 64 + mi * 16 + g + 8 * hh;
                float sum = red_s[row] + red_s[128 + row] + red_s[256 + row] + red_s[384 + row];
                lrow[mi][hh] = lrow[mi][hh] * fsc[mi][hh] + sum;
            }
            #pragma unroll
            for (int ni = 0; ni < 4; ni++) {
                o[mi][ni][0] *= fsc[mi][0];
                o[mi][ni][1] *= fsc[mi][0];
                o[mi][ni][2] *= fsc[mi][1];
                o[mi][ni][3] *= fsc[mi][1];
            }
        }

        #pragma unroll
        for (int ks = 0; ks < 16; ks++) {
            const int kb = ks * 8;
            uint32_t af[4][4], bf[4][2];
            #pragma unroll
            for (int mi = 0; mi < 4; mi++) {
                const float* base = KPs + (wm * 64 + mi * 16 + g) * LDP + kb + t;
                af[mi][0] = __float_as_uint(base[0]);
                af[mi][1] = __float_as_uint(base[8 * LDP]);
                af[mi][2] = __float_as_uint(base[4]);
                af[mi][3] = __float_as_uint(base[8 * LDP + 4]);
            }
            #pragma unroll
            for (int ni = 0; ni < 4; ni++) {
                const int n = wn * 32 + ni * 8 + g;
                bf[ni][0] = __float_as_uint(Vs[(kb + t) * LDP + n]);
                bf[ni][1] = __float_as_uint(Vs[(kb + t + 4) * LDP + n]);
            }
            #pragma unroll
            for (int mi = 0; mi < 4; mi++)
                #pragma unroll
                for (int ni = 0; ni < 4; ni++)
                    mma_tf32(o[mi][ni], af[mi], bf[ni]);
        }
        __syncthreads();
    }

    const size_t orow = (size_t)(b * SEQL + qt * 128);
    #pragma unroll
    for (int mi = 0; mi < 4; mi++) {
        const float i0 = 1.0f / lrow[mi][0];
        const float i1 = 1.0f / lrow[mi][1];
        const int r0 = wm * 64 + mi * 16 + g;
        #pragma unroll
        for (int ni = 0; ni < 4; ni++) {
            const int cc = h * DHEAD + wn * 32 + ni * 8 + 2 * t;
            *(float2*)(attn_out + (orow + r0) * DEMB + cc) =
                make_float2(tf32r(o[mi][ni][0] * i0), tf32r(o[mi][ni][1] * i0));
            *(float2*)(attn_out + (orow + r0 + 8) * DEMB + cc) =
                make_float2(tf32r(o[mi][ni][2] * i1), tf32r(o[mi][ni][3] * i1));
        }
    }
}

// ================================================================
// Launcher
// ================================================================
extern "C" void kernel_launch(void* const* d_in, const int* in_sizes, int n_in,
                              void* d_out, int out_size)
{
    (void)in_sizes; (void)n_in; (void)out_size;
    const float* x     = (const float*)d_in[0];
    const float* w_in  = (const float*)d_in[1];
    const float* b_in  = (const float*)d_in[2];
    const float* w_out = (const float*)d_in[3];
    const float* b_out = (const float*)d_in[4];
    float* out = (float*)d_out;

    void *qkv_p, *attn_p, *xtf_p, *wT1_p, *wT2_p;
    cudaGetSymbolAddress(&qkv_p,  g_qkv);
    cudaGetSymbolAddress(&attn_p, g_attn);
    cudaGetSymbolAddress(&xtf_p,  g_xtf);
    cudaGetSymbolAddress(&wT1_p,  g_wT1);
    cudaGetSymbolAddress(&wT2_p,  g_wT2);

    cudaFuncSetAttribute(flash_mma_kernel,
                         cudaFuncAttributeMaxDynamicSharedMemorySize, FLASH_SMEM);
    cudaFuncSetAttribute(tf32_mma_gemm_kernel,
                         cudaFuncAttributeMaxDynamicSharedMemorySize, GEMM_SMEM);

    // prep: wT1 = tf32(w_in^T), wT2 = tf32(w_out^T), xtf = tf32(x)
    transpose_tf32_kernel<<<dim3(D3 / 32, DEMB / 32), dim3(32, 8)>>>(w_in, (float*)wT1_p, DEMB, D3);
    transpose_tf32_kernel<<<dim3(DEMB / 32, DEMB / 32), dim3(32, 8)>>>(w_out, (float*)wT2_p, DEMB, DEMB);
    conv_tf32_kernel<<<(NTOK * DEMB / 4 + 255) / 256, 256>>>(x, (float*)xtf_p, NTOK * DEMB / 4);

    // 1) qkv = x @ w_in + b_in  (tf32-rounded out; Q cols pre-scaled by QSC)
    tf32_mma_gemm_kernel<<<dim3(NTOK / 128, D3 / 128), 256, GEMM_SMEM>>>(
        (const float*)xtf_p, (const float*)wT1_p, b_in, (float*)qkv_p,
        NTOK, D3, DEMB, DEMB, 1);

    // 2) causal flash attention (mma.sync tf32) -> g_attn (tf32-rounded)
    flash_mma_kernel<<<dim3(SEQL / 128, NHEADS, BATCH), 256, FLASH_SMEM>>>(
        (const float*)qkv_p, (float*)attn_p);

    // 3) out = attn @ w_out + b_out  (full fp32 out)
    tf32_mma_gemm_kernel<<<dim3(NTOK / 128, DEMB / 128), 256, GEMM_SMEM>>>(
        (const float*)attn_p, (const float*)wT2_p, b_out, out,
        NTOK, DEMB, DEMB, 0, 0);
}

// round 7
// speedup vs baseline: 1.1154x; 1.0433x over previous
#include <cuda_runtime.h>
#include <math.h>
#include <stdint.h>

#define BATCH   2
#define SEQL    2048
#define DEMB    2048
#define NHEADS  16
#define DHEAD   128
#define NTOK    (BATCH * SEQL)       // 4096
#define D3      (3 * DEMB)           // 6144

// combined score scale: log2(e)/sqrt(128), folded into Q at GEMM1 epilogue
#define QSC 0.1275174446f
#define NEGINF __int_as_float(0xff800000)

typedef unsigned long long ull;

// -------- scratch (__device__ globals; no allocs allowed) --------
__device__ float g_qkv [(size_t)NTOK * D3];     // 96 MB (tf32, Q pre-scaled)
__device__ float g_attn[(size_t)NTOK * DEMB];   // 32 MB (tf32-rounded)
__device__ float g_xtf [(size_t)NTOK * DEMB];   // 32 MB (tf32-rounded x)
__device__ float g_wT1 [(size_t)D3   * DEMB];   // 48 MB (w_in^T, tf32)
__device__ float g_wT2 [(size_t)DEMB * DEMB];   // 16 MB (w_out^T, tf32)

// ---------------- helpers ----------------
__device__ __forceinline__ uint32_t smem_u32(const void* p) {
    uint32_t a;
    asm("{ .reg .u64 t; cvta.to.shared.u64 t, %1; cvt.u32.u64 %0, t; }" : "=r"(a) : "l"(p));
    return a;
}
__device__ __forceinline__ float tf32r(float f) {
    uint32_t u = __float_as_uint(f);
    asm("cvt.rna.tf32.f32 %0, %0;" : "+r"(u));
    return __uint_as_float(u);
}
__device__ __forceinline__ float ex2(float x) {
    float y; asm("ex2.approx.f32 %0, %1;" : "=f"(y) : "f"(x)); return y;
}
__device__ __forceinline__ void cp_async16(uint32_t dst, const void* src) {
    asm volatile("cp.async.cg.shared.global [%0], [%1], 16;" :: "r"(dst), "l"(src) : "memory");
}
#define CP_COMMIT() asm volatile("cp.async.commit_group;" ::: "memory")
#define CP_WAIT(n)  asm volatile("cp.async.wait_group %0;" :: "n"(n) : "memory")

__device__ __forceinline__ void mma_tf32(float* c, const uint32_t* a, const uint32_t* b) {
    asm volatile(
        "mma.sync.aligned.m16n8k8.row.col.f32.tf32.tf32.f32 "
        "{%0,%1,%2,%3}, {%4,%5,%6,%7}, {%8,%9}, {%0,%1,%2,%3};"
        : "+f"(c[0]), "+f"(c[1]), "+f"(c[2]), "+f"(c[3])
        : "r"(a[0]), "r"(a[1]), "r"(a[2]), "r"(a[3]), "r"(b[0]), "r"(b[1]));
}
// tf32 fragments via b16 ldmatrix: 8x8 b16 tile == 8x4 tf32 tile; thread l
// receives the 32-bit chunk at (row l/4, tf32-col l%4) — exactly the mma layout.
__device__ __forceinline__ void ldsm_x4(uint32_t* r, uint32_t addr) {
    asm volatile("ldmatrix.sync.aligned.m8n8.x4.shared.b16 {%0,%1,%2,%3}, [%4];"
        : "=r"(r[0]), "=r"(r[1]), "=r"(r[2]), "=r"(r[3]) : "r"(addr));
}
__device__ __forceinline__ void ldsm_x2(uint32_t* r, uint32_t addr) {
    asm volatile("ldmatrix.sync.aligned.m8n8.x2.shared.b16 {%0,%1}, [%2];"
        : "=r"(r[0]), "=r"(r[1]) : "r"(addr));
}

// ================================================================
// Prep kernels: tf32-round inputs, transpose weights to [N][K]
// ================================================================
__global__ void transpose_tf32_kernel(const float* __restrict__ src, float* __restrict__ dst,
                                      int R, int C) {
    __shared__ float tile[32][33];
    int bx = blockIdx.x * 32, by = blockIdx.y * 32;
    int x = bx + threadIdx.x;
    for (int i = threadIdx.y; i < 32; i += 8)
        tile[i][threadIdx.x] = src[(size_t)(by + i) * C + x];
    __syncthreads();
    int ox = by + threadIdx.x;
    for (int i = threadIdx.y; i < 32; i += 8)
        dst[(size_t)(bx + i) * R + ox] = tf32r(tile[threadIdx.x][i]);
}

__global__ void conv_tf32_kernel(const float* __restrict__ src, float* __restrict__ dst, int n4) {
    int i = blockIdx.x * blockDim.x + threadIdx.x;
    if (i < n4) {
        float4 v = ((const float4*)src)[i];
        v.x = tf32r(v.x); v.y = tf32r(v.y); v.z = tf32r(v.z); v.w = tf32r(v.w);
        ((float4*)dst)[i] = v;
    }
}

// ================================================================
// tf32 mma.sync GEMM: C[M,N] = A[M,K] @ Bt[N,K]^T + bias[N]
// CTA 128x128, 8 warps (warp tile 64x32), K-chunk 32, 3-stage cp.async,
// ldmatrix fragment loads. 2 CTAs/SM.
// ================================================================
#define LDT 36
#define STG_F (2 * 128 * LDT)                            // floats per stage
#define GEMM_SMEM (3 * STG_F * (int)sizeof(float))       // 110592 B

__global__ __launch_bounds__(256, 2) void tf32_mma_gemm_kernel(
    const float* __restrict__ A, const float* __restrict__ Bt,
    const float* __restrict__ bias, float* __restrict__ C,
    int M, int N, int K, int qcols, int round_out)
{
    extern __shared__ float sm[];
    const int tid  = threadIdx.x;
    const int lane = tid & 31;
    const int wid  = tid >> 5;
    const int wm = wid >> 2;           // 0..1  -> 64-row slab
    const int wn = wid & 3;            // 0..3  -> 32-col slab
    const int g = lane >> 2, t = lane & 3;
    const int bm = blockIdx.x * 128;
    const int bn = blockIdx.y * 128;
    const int nchunks = K >> 5;

    // ldmatrix per-thread row assignments
    const int a_row  = (lane & 7) + ((lane >> 3) & 1) * 8;  // row within 16-row tile
    const int a_koff = (lane >> 4) * 4;                     // tf32 col half
    const int b_row  = lane & 7;
    const int b_koff = ((lane >> 3) & 1) * 4;

    const uint32_t smb = smem_u32(sm);

    float acc[4][4][4];
    #pragma unroll
    for (int mi = 0; mi < 4; mi++)
        #pragma unroll
        for (int ni = 0; ni < 4; ni++)
            #pragma unroll
            for (int q = 0; q < 4; q++) acc[mi][ni][q] = 0.0f;

    auto load_stage = [&](int c, int p) {
        const int kb = c << 5;
        float* dstA = sm + p * STG_F;
        float* dstB = dstA + 128 * LDT;
        const int row = tid >> 3;               // 0..31
        const int c4  = (tid & 7) << 2;         // 0..28
        #pragma unroll
        for (int i = 0; i < 4; i++) {
            int r = row + i * 32;               // 0..127
            cp_async16(smem_u32(dstA + r * LDT + c4),
                       A + (size_t)(bm + r) * K + kb + c4);
            cp_async16(smem_u32(dstB + r * LDT + c4),
                       Bt + (size_t)(bn + r) * K + kb + c4);
        }
        CP_COMMIT();
    };

    load_stage(0, 0);
    if (nchunks > 1) load_stage(1, 1);

    for (int c = 0; c < nchunks; c++) {
        if (c + 1 < nchunks) { CP_WAIT(1); } else { CP_WAIT(0); }
        __syncthreads();                // stage c visible; compute c-1 done everywhere

        if (c + 2 < nchunks) load_stage(c + 2, (c + 2) % 3);

        const uint32_t sAu = smb + (uint32_t)((c % 3) * STG_F) * 4u;
        const uint32_t sBu = sAu + 128u * LDT * 4u;
        #pragma unroll
        for (int ks = 0; ks < 4; ks++) {
            const int kb = ks * 8;
            uint32_t af[4][4], bf[4][2];
            #pragma unroll
            for (int mi = 0; mi < 4; mi++)
                ldsm_x4(af[mi],
                    sAu + (uint32_t)(((wm * 64 + mi * 16 + a_row) * LDT) + kb + a_koff) * 4u);
            #pragma unroll
            for (int ni = 0; ni < 4; ni++)
                ldsm_x2(bf[ni],
                    sBu + (uint32_t)(((wn * 32 + ni * 8 + b_row) * LDT) + kb + b_koff) * 4u);
            #pragma unroll
            for (int mi = 0; mi < 4; mi++)
                #pragma unroll
                for (int ni = 0; ni < 4; ni++)
                    mma_tf32(acc[mi][ni], af[mi], bf[ni]);
        }
    }
    __syncthreads();

    // ---- epilogue ----
    #pragma unroll
    for (int mi = 0; mi < 4; mi++) {
        const int r0 = bm + wm * 64 + mi * 16 + g;
        #pragma unroll
        for (int ni = 0; ni < 4; ni++) {
            const int n = bn + wn * 32 + ni * 8 + t * 2;
            const float sc = (n < qcols) ? QSC : 1.0f;
            float2 bv = *(const float2*)(bias + n);
            float v0 = (acc[mi][ni][0] + bv.x) * sc;
            float v1 = (acc[mi][ni][1] + bv.y) * sc;
            float v2 = (acc[mi][ni][2] + bv.x) * sc;
            float v3 = (acc[mi][ni][3] + bv.y) * sc;
            if (round_out) { v0 = tf32r(v0); v1 = tf32r(v1); v2 = tf32r(v2); v3 = tf32r(v3); }
            *(float2*)(C + (size_t)r0 * N + n)       = make_float2(v0, v1);
            *(float2*)(C + (size_t)(r0 + 8) * N + n) = make_float2(v2, v3);
        }
    }
}

// ================================================================
// Flash attention on mma.sync tf32, ldmatrix for Q/K/P fragments.
// ================================================================
#define LDP 132
#define FL_K  (128 * LDP)
#define FL_V  (2 * 128 * LDP)
#define FL_RM (3 * 128 * LDP)
#define FL_RS (FL_RM + 512)
#define FLASH_SMEM ((FL_RS + 512) * (int)sizeof(float))   // 206848 B

__global__ __launch_bounds__(256, 1) void flash_mma_kernel(
    const float* __restrict__ qkv, float* __restrict__ attn_out)
{
    extern __shared__ float sm[];
    float* Qs    = sm;
    float* KPs   = sm + FL_K;
    float* Vs    = sm + FL_V;
    float* red_m = sm + FL_RM;
    float* red_s = sm + FL_RS;

    const int qt  = (int)gridDim.x - 1 - (int)blockIdx.x;   // heavy first
    const int h   = blockIdx.y;
    const int b   = blockIdx.z;
    const int tid  = threadIdx.x;
    const int lane = tid & 31;
    const int wid  = tid >> 5;
    const int wm = wid >> 2, wn = wid & 3;
    const int g = lane >> 2, t = lane & 3;

    const int a_row  = (lane & 7) + ((lane >> 3) & 1) * 8;
    const int a_koff = (lane >> 4) * 4;
    const int b_row  = lane & 7;
    const int b_koff = ((lane >> 3) & 1) * 4;

    const uint32_t smb  = smem_u32(sm);
    const uint32_t Qsu  = smb;
    const uint32_t KPsu = smb + (uint32_t)FL_K * 4u;

    const float* qbase = qkv + (size_t)(b * SEQL + qt * 128) * D3 + h * DHEAD;
    #pragma unroll
    for (int i = 0; i < 16; i++) {
        int idx = tid + i * 256;
        int r  = idx >> 5;
        int c4 = (idx & 31) * 4;
        cp_async16(smem_u32(Qs + r * LDP + c4), qbase + (size_t)r * D3 + c4);
    }
    CP_COMMIT();

    float o[4][4][4];
    #pragma unroll
    for (int mi = 0; mi < 4; mi++)
        #pragma unroll
        for (int ni = 0; ni < 4; ni++)
            #pragma unroll
            for (int q = 0; q < 4; q++) o[mi][ni][q] = 0.0f;
    float mrow[4][2], lrow[4][2];
    #pragma unroll
    for (int mi = 0; mi < 4; mi++) {
        mrow[mi][0] = NEGINF; mrow[mi][1] = NEGINF;
        lrow[mi][0] = 0.0f;   lrow[mi][1] = 0.0f;
    }

    for (int jt = 0; jt <= qt; jt++) {
        const float* kbase = qkv + (size_t)(b * SEQL + jt * 128) * D3 + DEMB + h * DHEAD;
        #pragma unroll
        for (int i = 0; i < 16; i++) {
            int idx = tid + i * 256;
            int r  = idx >> 5;
            int c4 = (idx & 31) * 4;
            cp_async16(smem_u32(KPs + r * LDP + c4), kbase + (size_t)r * D3 + c4);
        }
        CP_COMMIT();
        #pragma unroll
        for (int i = 0; i < 16; i++) {
            int idx = tid + i * 256;
            int r  = idx >> 5;
            int c4 = (idx & 31) * 4;
            cp_async16(smem_u32(Vs + r * LDP + c4), kbase + DEMB + (size_t)r * D3 + c4);
        }
        CP_COMMIT();
        CP_WAIT(1);
        __syncthreads();

        float s[4][4][4];
        #pragma unroll
        for (int mi = 0; mi < 4; mi++)
            #pragma unroll
            for (int ni = 0; ni < 4; ni++)
                #pragma unroll
                for (int q = 0; q < 4; q++) s[mi][ni][q] = 0.0f;

        #pragma unroll
        for (int ks = 0; ks < 16; ks++) {
            const int kb = ks * 8;
            uint32_t af[4][4], bf[4][2];
            #pragma unroll
            for (int mi = 0; mi < 4; mi++)
                ldsm_x4(af[mi],
                    Qsu + (uint32_t)(((wm * 64 + mi * 16 + a_row) * LDP) + kb + a_koff) * 4u);
            #pragma unroll
            for (int ni = 0; ni < 4; ni++)
                ldsm_x2(bf[ni],
                    KPsu + (uint32_t)(((wn * 32 + ni * 8 + b_row) * LDP) + kb + b_koff) * 4u);
            #pragma unroll
            for (int mi = 0; mi < 4; mi++)
                #pragma unroll
                for (int ni = 0; ni < 4; ni++)
                    mma_tf32(s[mi][ni], af[mi], bf[ni]);
        }

        if (jt == qt) {
            #pragma unroll
            for (int mi = 0; mi < 4; mi++) {
                const int r0 = wm * 64 + mi * 16 + g;
                #pragma unroll
                for (int ni = 0; ni < 4; ni++) {
                    const int c = wn * 32 + ni * 8 + 2 * t;
                    if (c     > r0)     s[mi][ni][0] = NEGINF;
                    if (c + 1 > r0)     s[mi][ni][1] = NEGINF;
                    if (c     > r0 + 8) s[mi][ni][2] = NEGINF;
                    if (c + 1 > r0 + 8) s[mi][ni][3] = NEGINF;
                }
            }
        }

        float mt[4][2];
        #pragma unroll
        for (int mi = 0; mi < 4; mi++) {
            float a = fmaxf(s[mi][0][0], s[mi][0][1]);
            float bq = fmaxf(s[mi][0][2], s[mi][0][3]);
            #pragma unroll
            for (int ni = 1; ni < 4; ni++) {
                a  = fmaxf(a,  fmaxf(s[mi][ni][0], s[mi][ni][1]));
                bq = fmaxf(bq, fmaxf(s[mi][ni][2], s[mi][ni][3]));
            }
            mt[mi][0] = a; mt[mi][1] = bq;
        }
        #pragma unroll
        for (int off = 1; off <= 2; off <<= 1) {
            #pragma unroll
            for (int mi = 0; mi < 4; mi++) {
                mt[mi][0] = fmaxf(mt[mi][0], __shfl_xor_sync(0xffffffffu, mt[mi][0], off));
                mt[mi][1] = fmaxf(mt[mi][1], __shfl_xor_sync(0xffffffffu, mt[mi][1], off));
            }
        }
        if (t == 0) {
            #pragma unroll
            for (int mi = 0; mi < 4; mi++) {
                red_m[wn * 128 + wm * 64 + mi * 16 + g]     = mt[mi][0];
                red_m[wn * 128 + wm * 64 + mi * 16 + g + 8] = mt[mi][1];
            }
        }
        __syncthreads();

        float mnew[4][2], fsc[4][2];
        #pragma unroll
        for (int mi = 0; mi < 4; mi++) {
            #pragma unroll
            for (int hh = 0; hh < 2; hh++) {
                const int row = wm * 64 + mi * 16 + g + 8 * hh;
                float v = fmaxf(fmaxf(red_m[row], red_m[128 + row]),
                                fmaxf(red_m[256 + row], red_m[384 + row]));
                float mn = fmaxf(mrow[mi][hh], v);
                fsc[mi][hh]  = ex2(mrow[mi][hh] - mn);
                mnew[mi][hh] = mn;
                mrow[mi][hh] = mn;
            }
        }

        float rs[4][2];
        #pragma unroll
        for (int mi = 0; mi < 4; mi++) { rs[mi][0] = 0.0f; rs[mi][1] = 0.0f; }
        #pragma unroll
        for (int mi = 0; mi < 4; mi++) {
            #pragma unroll
            for (int ni = 0; ni < 4; ni++) {
                s[mi][ni][0] = ex2(s[mi][ni][0] - mnew[mi][0]);
                s[mi][ni][1] = ex2(s[mi][ni][1] - mnew[mi][0]);
                s[mi][ni][2] = ex2(s[mi][ni][2] - mnew[mi][1]);
                s[mi][ni][3] = ex2(s[mi][ni][3] - mnew[mi][1]);
                rs[mi][0] += s[mi][ni][0] + s[mi][ni][1];
                rs[mi][1] += s[mi][ni][2] + s[mi][ni][3];
            }
        }
        #pragma unroll
        for (int off = 1; off <= 2; off <<= 1) {
            #pragma unroll
            for (int mi = 0; mi < 4; mi++) {
                rs[mi][0] += __shfl_xor_sync(0xffffffffu, rs[mi][0], off);
                rs[mi][1] += __shfl_xor_sync(0xffffffffu, rs[mi][1], off);
            }
        }
        if (t == 0) {
            #pragma unroll
            for (int mi = 0; mi < 4; mi++) {
                red_s[wn * 128 + wm * 64 + mi * 16 + g]     = rs[mi][0];
                red_s[wn * 128 + wm * 64 + mi * 16 + g + 8] = rs[mi][1];
            }
        }

        #pragma unroll
        for (int mi = 0; mi < 4; mi++) {
            const int r0 = wm * 64 + mi * 16 + g;
            #pragma unroll
            for (int ni = 0; ni < 4; ni++) {
                const int c = wn * 32 + ni * 8 + 2 * t;
                *(float2*)&KPs[r0 * LDP + c] =
                    make_float2(tf32r(s[mi][ni][0]), tf32r(s[mi][ni][1]));
                *(float2*)&KPs[(r0 + 8) * LDP + c] =
                    make_float2(tf32r(s[mi][ni][2]), tf32r(s[mi][ni][3]));
            }
        }
        CP_WAIT(0);
        __syncthreads();

        #pragma unroll
        for (int mi = 0; mi < 4; mi++) {
            #pragma unroll
            for (int hh = 0; hh < 2; hh++) {
                const int row = wm * 64 + mi * 16 + g + 8 * hh;
                float sum = red_s[row] + red_s[128 + row] + red_s[256 + row] + red_s[384 + row];
                lrow[mi][hh] = lrow[mi][hh] * fsc[mi][hh] + sum;
            }
            #pragma unroll
            for (int ni = 0; ni < 4; ni++) {
                o[mi][ni][0] *= fsc[mi][0];
                o[mi][ni][1] *= fsc[mi][0];
                o[mi][ni][2] *= fsc[mi][1];
                o[mi][ni][3] *= fsc[mi][1];
            }
        }

        #pragma unroll
        for (int ks = 0; ks < 16; ks++) {
            const int kb = ks * 8;
            uint32_t af[4][4], bf[4][2];
            #pragma unroll
            for (int mi = 0; mi < 4; mi++)
                ldsm_x4(af[mi],
                    KPsu + (uint32_t)(((wm * 64 + mi * 16 + a_row) * LDP) + kb + a_koff) * 4u);
            #pragma unroll
            for (int ni = 0; ni < 4; ni++) {
                const int n = wn * 32 + ni * 8 + g;
                bf[ni][0] = __float_as_uint(Vs[(kb + t) * LDP + n]);
                bf[ni][1] = __float_as_uint(Vs[(kb + t + 4) * LDP + n]);
            }
            #pragma unroll
            for (int mi = 0; mi < 4; mi++)
                #pragma unroll
                for (int ni = 0; ni < 4; ni++)
                    mma_tf32(o[mi][ni], af[mi], bf[ni]);
        }
        __syncthreads();
    }

    const size_t orow = (size_t)(b * SEQL + qt * 128);
    #pragma unroll
    for (int mi = 0; mi < 4; mi++) {
        const float i0 = 1.0f / lrow[mi][0];
        const float i1 = 1.0f / lrow[mi][1];
        const int r0 = wm * 64 + mi * 16 + g;
        #pragma unroll
        for (int ni = 0; ni < 4; ni++) {
            const int cc = h * DHEAD + wn * 32 + ni * 8 + 2 * t;
            *(float2*)(attn_out + (orow + r0) * DEMB + cc) =
                make_float2(tf32r(o[mi][ni][0] * i0), tf32r(o[mi][ni][1] * i0));
            *(float2*)(attn_out + (orow + r0 + 8) * DEMB + cc) =
                make_float2(tf32r(o[mi][ni][2] * i1), tf32r(o[mi][ni][3] * i1));
        }
    }
}

// ================================================================
// Launcher
// ================================================================
extern "C" void kernel_launch(void* const* d_in, const int* in_sizes, int n_in,
                              void* d_out, int out_size)
{
    (void)in_sizes; (void)n_in; (void)out_size;
    const float* x     = (const float*)d_in[0];
    const float* w_in  = (const float*)d_in[1];
    const float* b_in  = (const float*)d_in[2];
    const float* w_out = (const float*)d_in[3];
    const float* b_out = (const float*)d_in[4];
    float* out = (float*)d_out;

    void *qkv_p, *attn_p, *xtf_p, *wT1_p, *wT2_p;
    cudaGetSymbolAddress(&qkv_p,  g_qkv);
    cudaGetSymbolAddress(&attn_p, g_attn);
    cudaGetSymbolAddress(&xtf_p,  g_xtf);
    cudaGetSymbolAddress(&wT1_p,  g_wT1);
    cudaGetSymbolAddress(&wT2_p,  g_wT2);

    cudaFuncSetAttribute(flash_mma_kernel,
                         cudaFuncAttributeMaxDynamicSharedMemorySize, FLASH_SMEM);
    cudaFuncSetAttribute(tf32_mma_gemm_kernel,
                         cudaFuncAttributeMaxDynamicSharedMemorySize, GEMM_SMEM);

    // prep: wT1 = tf32(w_in^T), wT2 = tf32(w_out^T), xtf = tf32(x)
    transpose_tf32_kernel<<<dim3(D3 / 32, DEMB / 32), dim3(32, 8)>>>(w_in, (float*)wT1_p, DEMB, D3);
    transpose_tf32_kernel<<<dim3(DEMB / 32, DEMB / 32), dim3(32, 8)>>>(w_out, (float*)wT2_p, DEMB, DEMB);
    conv_tf32_kernel<<<(NTOK * DEMB / 4 + 255) / 256, 256>>>(x, (float*)xtf_p, NTOK * DEMB / 4);

    // 1) qkv = x @ w_in + b_in  (tf32-rounded out; Q cols pre-scaled by QSC)
    tf32_mma_gemm_kernel<<<dim3(NTOK / 128, D3 / 128), 256, GEMM_SMEM>>>(
        (const float*)xtf_p, (const float*)wT1_p, b_in, (float*)qkv_p,
        NTOK, D3, DEMB, DEMB, 1);

    // 2) causal flash attention (mma.sync tf32) -> g_attn (tf32-rounded)
    flash_mma_kernel<<<dim3(SEQL / 128, NHEADS, BATCH), 256, FLASH_SMEM>>>(
        (const float*)qkv_p, (float*)attn_p);

    // 3) out = attn @ w_out + b_out  (full fp32 out)
    tf32_mma_gemm_kernel<<<dim3(NTOK / 128, DEMB / 128), 256, GEMM_SMEM>>>(
        (const float*)attn_p, (const float*)wT2_p, b_out, out,
        NTOK, DEMB, DEMB, 0, 0);
}

// round 8
// speedup vs baseline: 1.9552x; 1.7529x over previous
#include <cuda_runtime.h>
#include <cuda_fp16.h>
#include <math.h>
#include <stdint.h>

#define BATCH   2
#define SEQL    2048
#define DEMB    2048
#define NHEADS  16
#define DHEAD   128
#define NTOK    (BATCH * SEQL)       // 4096
#define D3      (3 * DEMB)           // 6144

// combined score scale: log2(e)/sqrt(128), folded into Q at GEMM1 epilogue
#define QSC 0.1275174446f
#define NEGINF __int_as_float(0xff800000)

// -------- scratch (__device__ globals; no allocs allowed) --------
__device__ __half g_qkv [(size_t)NTOK * D3];     // 48 MB (fp16, Q pre-scaled)
__device__ __half g_attn[(size_t)NTOK * DEMB];   // 16 MB
__device__ __half g_xh  [(size_t)NTOK * DEMB];   // 16 MB (fp16 x)
__device__ __half g_wT1 [(size_t)D3   * DEMB];   // 24 MB (w_in^T fp16)
__device__ __half g_wT2 [(size_t)DEMB * DEMB];   //  8 MB (w_out^T fp16)

// ---------------- helpers ----------------
__device__ __forceinline__ uint32_t smem_u32(const void* p) {
    uint32_t a;
    asm("{ .reg .u64 t; cvta.to.shared.u64 t, %1; cvt.u32.u64 %0, t; }" : "=r"(a) : "l"(p));
    return a;
}
__device__ __forceinline__ float ex2(float x) {
    float y; asm("ex2.approx.f32 %0, %1;" : "=f"(y) : "f"(x)); return y;
}
__device__ __forceinline__ void cp_async16(uint32_t dst, const void* src) {
    asm volatile("cp.async.cg.shared.global [%0], [%1], 16;" :: "r"(dst), "l"(src) : "memory");
}
#define CP_COMMIT() asm volatile("cp.async.commit_group;" ::: "memory")
#define CP_WAIT(n)  asm volatile("cp.async.wait_group %0;" :: "n"(n) : "memory")

__device__ __forceinline__ void mma_f16(float* c, const uint32_t* a, const uint32_t* b) {
    asm volatile(
        "mma.sync.aligned.m16n8k16.row.col.f32.f16.f16.f32 "
        "{%0,%1,%2,%3}, {%4,%5,%6,%7}, {%8,%9}, {%0,%1,%2,%3};"
        : "+f"(c[0]), "+f"(c[1]), "+f"(c[2]), "+f"(c[3])
        : "r"(a[0]), "r"(a[1]), "r"(a[2]), "r"(a[3]), "r"(b[0]), "r"(b[1]));
}
__device__ __forceinline__ void ldsm_x4(uint32_t* r, uint32_t addr) {
    asm volatile("ldmatrix.sync.aligned.m8n8.x4.shared.b16 {%0,%1,%2,%3}, [%4];"
        : "=r"(r[0]), "=r"(r[1]), "=r"(r[2]), "=r"(r[3]) : "r"(addr));
}
__device__ __forceinline__ void ldsm_x2(uint32_t* r, uint32_t addr) {
    asm volatile("ldmatrix.sync.aligned.m8n8.x2.shared.b16 {%0,%1}, [%2];"
        : "=r"(r[0]), "=r"(r[1]) : "r"(addr));
}
__device__ __forceinline__ void ldsm_x2_trans(uint32_t* r, uint32_t addr) {
    asm volatile("ldmatrix.sync.aligned.m8n8.x2.trans.shared.b16 {%0,%1}, [%2];"
        : "=r"(r[0]), "=r"(r[1]) : "r"(addr));
}

// ================================================================
// Prep kernels: fp16-convert x, transpose+convert weights to [N][K]
// ================================================================
__global__ void transpose_h_kernel(const float* __restrict__ src, __half* __restrict__ dst,
                                   int R, int C) {
    __shared__ float tile[32][33];
    int bx = blockIdx.x * 32, by = blockIdx.y * 32;
    int x = bx + threadIdx.x;
    for (int i = threadIdx.y; i < 32; i += 8)
        tile[i][threadIdx.x] = src[(size_t)(by + i) * C + x];
    __syncthreads();
    int ox = by + threadIdx.x;
    for (int i = threadIdx.y; i < 32; i += 8)
        dst[(size_t)(bx + i) * R + ox] = __float2half_rn(tile[threadIdx.x][i]);
}

__global__ void conv_h_kernel(const float* __restrict__ src, __half* __restrict__ dst, int n4) {
    int i = blockIdx.x * blockDim.x + threadIdx.x;
    if (i < n4) {
        float4 v = ((const float4*)src)[i];
        __half2 h0 = __floats2half2_rn(v.x, v.y);
        __half2 h1 = __floats2half2_rn(v.z, v.w);
        ((__half2*)dst)[2 * i]     = h0;
        ((__half2*)dst)[2 * i + 1] = h1;
    }
}

// ================================================================
// fp16 mma GEMM: C[M,N] = A[M,K] @ Bt[N,K]^T + bias[N]
// CTA 128x128, 8 warps (warp tile 64x32), K-chunk 64 halves,
// 3-stage cp.async, ldmatrix frags, 2 CTAs/SM.
// Output: Ch (fp16, cols<qcols scaled by QSC) or Cf (fp32).
// ================================================================
#define LDT 72                                           // halves per row (64 + 8 pad)
#define STG_H (256 * LDT)                                // halves per stage (A 128 + B 128)
#define GEMM_SMEM (3 * STG_H * 2)                        // 110592 B

__global__ __launch_bounds__(256, 2) void f16_mma_gemm_kernel(
    const __half* __restrict__ A, const __half* __restrict__ Bt,
    const float* __restrict__ bias, __half* __restrict__ Ch, float* __restrict__ Cf,
    int M, int N, int K, int qcols)
{
    extern __shared__ __half smh[];
    const int tid  = threadIdx.x;
    const int lane = tid & 31;
    const int wid  = tid >> 5;
    const int wm = wid >> 2;           // 0..1  -> 64-row slab
    const int wn = wid & 3;            // 0..3  -> 32-col slab
    const int g = lane >> 2, t = lane & 3;
    const int bm = blockIdx.x * 128;
    const int bn = blockIdx.y * 128;
    const int nchunks = K >> 6;        // K / 64

    const int a_row  = (lane & 7) + ((lane >> 3) & 1) * 8;
    const int a_koff = (lane >> 4) * 8;                  // halves (k8..15 half)
    const int b_row  = lane & 7;
    const int b_koff = ((lane >> 3) & 1) * 8;

    const uint32_t smb = smem_u32(smh);

    float acc[4][4][4];
    #pragma unroll
    for (int mi = 0; mi < 4; mi++)
        #pragma unroll
        for (int ni = 0; ni < 4; ni++)
            #pragma unroll
            for (int q = 0; q < 4; q++) acc[mi][ni][q] = 0.0f;

    auto load_stage = [&](int c, int p) {
        const int kb = c << 6;
        __half* dstA = smh + p * STG_H;
        __half* dstB = dstA + 128 * LDT;
        #pragma unroll
        for (int i = 0; i < 8; i++) {
            int idx = tid + i * 256;            // 0..2047
            int r   = idx >> 3;                 // 0..255
            int c8  = (idx & 7) * 8;            // halves, 0..56
            if (r < 128)
                cp_async16(smem_u32(dstA + r * LDT + c8),
                           A + (size_t)(bm + r) * K + kb + c8);
            else
                cp_async16(smem_u32(dstB + (r - 128) * LDT + c8),
                           Bt + (size_t)(bn + r - 128) * K + kb + c8);
        }
        CP_COMMIT();
    };

    load_stage(0, 0);
    if (nchunks > 1) load_stage(1, 1);

    for (int c = 0; c < nchunks; c++) {
        if (c + 1 < nchunks) { CP_WAIT(1); } else { CP_WAIT(0); }
        __syncthreads();

        if (c + 2 < nchunks) load_stage(c + 2, (c + 2) % 3);

        const uint32_t sAu = smb + (uint32_t)((c % 3) * STG_H) * 2u;
        const uint32_t sBu = sAu + 128u * LDT * 2u;
        #pragma unroll
        for (int ks = 0; ks < 4; ks++) {
            const int kb = ks * 16;             // halves
            uint32_t af[4][4], bf[4][2];
            #pragma unroll
            for (int mi = 0; mi < 4; mi++)
                ldsm_x4(af[mi],
                    sAu + (uint32_t)(((wm * 64 + mi * 16 + a_row) * LDT) + kb + a_koff) * 2u);
            #pragma unroll
            for (int ni = 0; ni < 4; ni++)
                ldsm_x2(bf[ni],
                    sBu + (uint32_t)(((wn * 32 + ni * 8 + b_row) * LDT) + kb + b_koff) * 2u);
            #pragma unroll
            for (int mi = 0; mi < 4; mi++)
                #pragma unroll
                for (int ni = 0; ni < 4; ni++)
                    mma_f16(acc[mi][ni], af[mi], bf[ni]);
        }
    }
    __syncthreads();

    // ---- epilogue ----
    #pragma unroll
    for (int mi = 0; mi < 4; mi++) {
        const int r0 = bm + wm * 64 + mi * 16 + g;
        #pragma unroll
        for (int ni = 0; ni < 4; ni++) {
            const int n = bn + wn * 32 + ni * 8 + t * 2;
            const float sc = (n < qcols) ? QSC : 1.0f;
            float2 bv = *(const float2*)(bias + n);
            float v0 = (acc[mi][ni][0] + bv.x) * sc;
            float v1 = (acc[mi][ni][1] + bv.y) * sc;
            float v2 = (acc[mi][ni][2] + bv.x) * sc;
            float v3 = (acc[mi][ni][3] + bv.y) * sc;
            if (Ch) {
                *(__half2*)(Ch + (size_t)r0 * N + n)       = __floats2half2_rn(v0, v1);
                *(__half2*)(Ch + (size_t)(r0 + 8) * N + n) = __floats2half2_rn(v2, v3);
            } else {
                *(float2*)(Cf + (size_t)r0 * N + n)       = make_float2(v0, v1);
                *(float2*)(Cf + (size_t)(r0 + 8) * N + n) = make_float2(v2, v3);
            }
        }
    }
}

// ================================================================
// Flash attention, fp16 mma (m16n8k16), fp16 smem tiles.
// CTA 256 thr / 8 warps; tile 128q x 128kv; dh = 128.
// ================================================================
#define LDH 136                                         // halves per row
#define FLB_Q  0
#define FLB_KP (128 * LDH * 2)
#define FLB_V  (2 * 128 * LDH * 2)
#define FLB_RM (3 * 128 * LDH * 2)                      // float[512]
#define FLB_RS (FLB_RM + 2048)
#define FLASH_SMEM (FLB_RS + 2048)                      // 108544 B

__global__ __launch_bounds__(256, 1) void flash_f16_kernel(
    const __half* __restrict__ qkv, __half* __restrict__ attn_out)
{
    extern __shared__ char smc[];
    __half* Qh   = (__half*)(smc + FLB_Q);
    __half* KPh  = (__half*)(smc + FLB_KP);
    __half* Vh   = (__half*)(smc + FLB_V);
    float* red_m = (float*)(smc + FLB_RM);
    float* red_s = (float*)(smc + FLB_RS);

    const int qt  = (int)gridDim.x - 1 - (int)blockIdx.x;   // heavy first
    const int h   = blockIdx.y;
    const int b   = blockIdx.z;
    const int tid  = threadIdx.x;
    const int lane = tid & 31;
    const int wid  = tid >> 5;
    const int wm = wid >> 2, wn = wid & 3;
    const int g = lane >> 2, t = lane & 3;

    const int a_row  = (lane & 7) + ((lane >> 3) & 1) * 8;
    const int a_koff = (lane >> 4) * 8;
    const int b_row  = lane & 7;
    const int b_koff = ((lane >> 3) & 1) * 8;
    const int v_row  = (lane & 7) + ((lane >> 3) & 1) * 8;   // trans: k-row within 16

    const uint32_t smb  = smem_u32(smc);
    const uint32_t Qu   = smb + FLB_Q;
    const uint32_t KPu  = smb + FLB_KP;
    const uint32_t Vu   = smb + FLB_V;

    // ---- Q tile load (once) ----
    const __half* qbase = qkv + (size_t)(b * SEQL + qt * 128) * D3 + h * DHEAD;
    #pragma unroll
    for (int i = 0; i < 8; i++) {
        int idx = tid + i * 256;            // 0..2047
        int r   = idx >> 4;                 // 0..127
        int c8  = (idx & 15) * 8;           // halves, 0..120
        cp_async16(smem_u32(Qh + r * LDH + c8), qbase + (size_t)r * D3 + c8);
    }
    CP_COMMIT();

    float o[4][4][4];
    #pragma unroll
    for (int mi = 0; mi < 4; mi++)
        #pragma unroll
        for (int ni = 0; ni < 4; ni++)
            #pragma unroll
            for (int q = 0; q < 4; q++) o[mi][ni][q] = 0.0f;
    float mrow[4][2], lrow[4][2];
    #pragma unroll
    for (int mi = 0; mi < 4; mi++) {
        mrow[mi][0] = NEGINF; mrow[mi][1] = NEGINF;
        lrow[mi][0] = 0.0f;   lrow[mi][1] = 0.0f;
    }

    for (int jt = 0; jt <= qt; jt++) {
        const __half* kbase = qkv + (size_t)(b * SEQL + jt * 128) * D3 + DEMB + h * DHEAD;
        #pragma unroll
        for (int i = 0; i < 8; i++) {
            int idx = tid + i * 256;
            int r   = idx >> 4;
            int c8  = (idx & 15) * 8;
            cp_async16(smem_u32(KPh + r * LDH + c8), kbase + (size_t)r * D3 + c8);
        }
        CP_COMMIT();
        #pragma unroll
        for (int i = 0; i < 8; i++) {
            int idx = tid + i * 256;
            int r   = idx >> 4;
            int c8  = (idx & 15) * 8;
            cp_async16(smem_u32(Vh + r * LDH + c8), kbase + DEMB + (size_t)r * D3 + c8);
        }
        CP_COMMIT();
        CP_WAIT(1);            // Q + K arrived (V may be in flight)
        __syncthreads();

        // ---- S = Q @ K^T : 8 k16-steps ----
        float s[4][4][4];
        #pragma unroll
        for (int mi = 0; mi < 4; mi++)
            #pragma unroll
            for (int ni = 0; ni < 4; ni++)
                #pragma unroll
                for (int q = 0; q < 4; q++) s[mi][ni][q] = 0.0f;

        #pragma unroll
        for (int ks = 0; ks < 8; ks++) {
            const int kb = ks * 16;
            uint32_t af[4][4], bf[4][2];
            #pragma unroll
            for (int mi = 0; mi < 4; mi++)
                ldsm_x4(af[mi],
                    Qu + (uint32_t)(((wm * 64 + mi * 16 + a_row) * LDH) + kb + a_koff) * 2u);
            #pragma unroll
            for (int ni = 0; ni < 4; ni++)
                ldsm_x2(bf[ni],
                    KPu + (uint32_t)(((wn * 32 + ni * 8 + b_row) * LDH) + kb + b_koff) * 2u);
            #pragma unroll
            for (int mi = 0; mi < 4; mi++)
                #pragma unroll
                for (int ni = 0; ni < 4; ni++)
                    mma_f16(s[mi][ni], af[mi], bf[ni]);
        }

        // ---- causal mask on diagonal tile ----
        if (jt == qt) {
            #pragma unroll
            for (int mi = 0; mi < 4; mi++) {
                const int r0 = wm * 64 + mi * 16 + g;
                #pragma unroll
                for (int ni = 0; ni < 4; ni++) {
                    const int c = wn * 32 + ni * 8 + 2 * t;
                    if (c     > r0)     s[mi][ni][0] = NEGINF;
                    if (c + 1 > r0)     s[mi][ni][1] = NEGINF;
                    if (c     > r0 + 8) s[mi][ni][2] = NEGINF;
                    if (c + 1 > r0 + 8) s[mi][ni][3] = NEGINF;
                }
            }
        }

        // ---- row max ----
        float mt[4][2];
        #pragma unroll
        for (int mi = 0; mi < 4; mi++) {
            float a = fmaxf(s[mi][0][0], s[mi][0][1]);
            float bq = fmaxf(s[mi][0][2], s[mi][0][3]);
            #pragma unroll
            for (int ni = 1; ni < 4; ni++) {
                a  = fmaxf(a,  fmaxf(s[mi][ni][0], s[mi][ni][1]));
                bq = fmaxf(bq, fmaxf(s[mi][ni][2], s[mi][ni][3]));
            }
            mt[mi][0] = a; mt[mi][1] = bq;
        }
        #pragma unroll
        for (int off = 1; off <= 2; off <<= 1) {
            #pragma unroll
            for (int mi = 0; mi < 4; mi++) {
                mt[mi][0] = fmaxf(mt[mi][0], __shfl_xor_sync(0xffffffffu, mt[mi][0], off));
                mt[mi][1] = fmaxf(mt[mi][1], __shfl_xor_sync(0xffffffffu, mt[mi][1], off));
            }
        }
        if (t == 0) {
            #pragma unroll
            for (int mi = 0; mi < 4; mi++) {
                red_m[wn * 128 + wm * 64 + mi * 16 + g]     = mt[mi][0];
                red_m[wn * 128 + wm * 64 + mi * 16 + g + 8] = mt[mi][1];
            }
        }
        __syncthreads();

        float mnew[4][2], fsc[4][2];
        #pragma unroll
        for (int mi = 0; mi < 4; mi++) {
            #pragma unroll
            for (int hh = 0; hh < 2; hh++) {
                const int row = wm * 64 + mi * 16 + g + 8 * hh;
                float v = fmaxf(fmaxf(red_m[row], red_m[128 + row]),
                                fmaxf(red_m[256 + row], red_m[384 + row]));
                float mn = fmaxf(mrow[mi][hh], v);
                fsc[mi][hh]  = ex2(mrow[mi][hh] - mn);
                mnew[mi][hh] = mn;
                mrow[mi][hh] = mn;
            }
        }

        // ---- exp + row sums ----
        float rs[4][2];
        #pragma unroll
        for (int mi = 0; mi < 4; mi++) { rs[mi][0] = 0.0f; rs[mi][1] = 0.0f; }
        #pragma unroll
        for (int mi = 0; mi < 4; mi++) {
            #pragma unroll
            for (int ni = 0; ni < 4; ni++) {
                s[mi][ni][0] = ex2(s[mi][ni][0] - mnew[mi][0]);
                s[mi][ni][1] = ex2(s[mi][ni][1] - mnew[mi][0]);
                s[mi][ni][2] = ex2(s[mi][ni][2] - mnew[mi][1]);
                s[mi][ni][3] = ex2(s[mi][ni][3] - mnew[mi][1]);
                rs[mi][0] += s[mi][ni][0] + s[mi][ni][1];
                rs[mi][1] += s[mi][ni][2] + s[mi][ni][3];
            }
        }
        #pragma unroll
        for (int off = 1; off <= 2; off <<= 1) {
            #pragma unroll
            for (int mi = 0; mi < 4; mi++) {
                rs[mi][0] += __shfl_xor_sync(0xffffffffu, rs[mi][0], off);
                rs[mi][1] += __shfl_xor_sync(0xffffffffu, rs[mi][1], off);
            }
        }
        if (t == 0) {
            #pragma unroll
            for (int mi = 0; mi < 4; mi++) {
                red_s[wn * 128 + wm * 64 + mi * 16 + g]     = rs[mi][0];
                red_s[wn * 128 + wm * 64 + mi * 16 + g + 8] = rs[mi][1];
            }
        }

        // ---- P (fp16) -> smem, reusing K buffer (safe: K reads done
        //      before the red_m __syncthreads above) ----
        #pragma unroll
        for (int mi = 0; mi < 4; mi++) {
            const int r0 = wm * 64 + mi * 16 + g;
            #pragma unroll
            for (int ni = 0; ni < 4; ni++) {
                const int c = wn * 32 + ni * 8 + 2 * t;
                *(__half2*)&KPh[r0 * LDH + c] =
                    __floats2half2_rn(s[mi][ni][0], s[mi][ni][1]);
                *(__half2*)&KPh[(r0 + 8) * LDH + c] =
                    __floats2half2_rn(s[mi][ni][2], s[mi][ni][3]);
            }
        }
        CP_WAIT(0);            // V arrived
        __syncthreads();       // P + V + red_s visible

        // ---- l update, O rescale ----
        #pragma unroll
        for (int mi = 0; mi < 4; mi++) {
            #pragma unroll
            for (int hh = 0; hh < 2; hh++) {
                const int row = wm * 64 + mi * 16 + g + 8 * hh;
                float sum = red_s[row] + red_s[128 + row] + red_s[256 + row] + red_s[384 + row];
                lrow[mi][hh] = lrow[mi][hh] * fsc[mi][hh] + sum;
            }
            #pragma unroll
            for (int ni = 0; ni < 4; ni++) {
                o[mi][ni][0] *= fsc[mi][0];
                o[mi][ni][1] *= fsc[mi][0];
                o[mi][ni][2] *= fsc[mi][1];
                o[mi][ni][3] *= fsc[mi][1];
            }
        }

        // ---- O += P @ V : 8 k16-steps; V via ldmatrix.trans ----
        #pragma unroll
        for (int ks = 0; ks < 8; ks++) {
            const int kb = ks * 16;
            uint32_t af[4][4], bf[4][2];
            #pragma unroll
            for (int mi = 0; mi < 4; mi++)
                ldsm_x4(af[mi],
                    KPu + (uint32_t)(((wm * 64 + mi * 16 + a_row) * LDH) + kb + a_koff) * 2u);
            #pragma unroll
            for (int ni = 0; ni < 4; ni++)
                ldsm_x2_trans(bf[ni],
                    Vu + (uint32_t)(((kb + v_row) * LDH) + wn * 32 + ni * 8) * 2u);
            #pragma unroll
            for (int mi = 0; mi < 4; mi++)
                #pragma unroll
                for (int ni = 0; ni < 4; ni++)
                    mma_f16(o[mi][ni], af[mi], bf[ni]);
        }
        __syncthreads();       // before next tile's cp.async overwrites KPh/Vh
    }

    // ---- epilogue: O /= l, fp16 out (feeds GEMM2) ----
    const size_t orow = (size_t)(b * SEQL + qt * 128);
    #pragma unroll
    for (int mi = 0; mi < 4; mi++) {
        const float i0 = 1.0f / lrow[mi][0];
        const float i1 = 1.0f / lrow[mi][1];
        const int r0 = wm * 64 + mi * 16 + g;
        #pragma unroll
        for (int ni = 0; ni < 4; ni++) {
            const int cc = h * DHEAD + wn * 32 + ni * 8 + 2 * t;
            *(__half2*)(attn_out + (orow + r0) * DEMB + cc) =
                __floats2half2_rn(o[mi][ni][0] * i0, o[mi][ni][1] * i0);
            *(__half2*)(attn_out + (orow + r0 + 8) * DEMB + cc) =
                __floats2half2_rn(o[mi][ni][2] * i1, o[mi][ni][3] * i1);
        }
    }
}

// ================================================================
// Launcher
// ================================================================
extern "C" void kernel_launch(void* const* d_in, const int* in_sizes, int n_in,
                              void* d_out, int out_size)
{
    (void)in_sizes; (void)n_in; (void)out_size;
    const float* x     = (const float*)d_in[0];
    const float* w_in  = (const float*)d_in[1];
    const float* b_in  = (const float*)d_in[2];
    const float* w_out = (const float*)d_in[3];
    const float* b_out = (const float*)d_in[4];
    float* out = (float*)d_out;

    void *qkv_p, *attn_p, *xh_p, *wT1_p, *wT2_p;
    cudaGetSymbolAddress(&qkv_p,  g_qkv);
    cudaGetSymbolAddress(&attn_p, g_attn);
    cudaGetSymbolAddress(&xh_p,   g_xh);
    cudaGetSymbolAddress(&wT1_p,  g_wT1);
    cudaGetSymbolAddress(&wT2_p,  g_wT2);

    cudaFuncSetAttribute(flash_f16_kernel,
                         cudaFuncAttributeMaxDynamicSharedMemorySize, FLASH_SMEM);
    cudaFuncSetAttribute(f16_mma_gemm_kernel,
                         cudaFuncAttributeMaxDynamicSharedMemorySize, GEMM_SMEM);

    // prep: wT1 = h(w_in^T), wT2 = h(w_out^T), xh = h(x)
    transpose_h_kernel<<<dim3(D3 / 32, DEMB / 32), dim3(32, 8)>>>(w_in, (__half*)wT1_p, DEMB, D3);
    transpose_h_kernel<<<dim3(DEMB / 32, DEMB / 32), dim3(32, 8)>>>(w_out, (__half*)wT2_p, DEMB, DEMB);
    conv_h_kernel<<<(NTOK * DEMB / 4 + 255) / 256, 256>>>(x, (__half*)xh_p, NTOK * DEMB / 4);

    // 1) qkv = x @ w_in + b_in  (fp16 out; Q cols pre-scaled by QSC)
    f16_mma_gemm_kernel<<<dim3(NTOK / 128, D3 / 128), 256, GEMM_SMEM>>>(
        (const __half*)xh_p, (const __half*)wT1_p, b_in,
        (__half*)qkv_p, nullptr, NTOK, D3, DEMB, DEMB);

    // 2) causal flash attention (fp16 mma) -> g_attn
    flash_f16_kernel<<<dim3(SEQL / 128, NHEADS, BATCH), 256, FLASH_SMEM>>>(
        (const __half*)qkv_p, (__half*)attn_p);

    // 3) out = attn @ w_out + b_out  (fp32 out)
    f16_mma_gemm_kernel<<<dim3(NTOK / 128, DEMB / 128), 256, GEMM_SMEM>>>(
        (const __half*)attn_p, (const __half*)wT2_p, b_out,
        nullptr, out, NTOK, DEMB, DEMB, 0);
}

// round 9
// speedup vs baseline: 2.1215x; 1.0851x over previous
#include <cuda_runtime.h>
#include <cuda_fp16.h>
#include <math.h>
#include <stdint.h>

#define BATCH   2
#define SEQL    2048
#define DEMB    2048
#define NHEADS  16
#define DHEAD   128
#define NTOK    (BATCH * SEQL)       // 4096
#define D3      (3 * DEMB)           // 6144

// combined score scale: log2(e)/sqrt(128), folded into Q at GEMM1 epilogue
#define QSC 0.1275174446f
#define NEGINF __int_as_float(0xff800000)

// -------- scratch (__device__ globals; no allocs allowed) --------
__device__ __half g_qkv [(size_t)NTOK * D3];     // 48 MB (fp16, Q pre-scaled)
__device__ __half g_attn[(size_t)NTOK * DEMB];   // 16 MB
__device__ __half g_xh  [(size_t)NTOK * DEMB];   // 16 MB (fp16 x)
__device__ __half g_wT1 [(size_t)D3   * DEMB];   // 24 MB (w_in^T fp16)
__device__ __half g_wT2 [(size_t)DEMB * DEMB];   //  8 MB (w_out^T fp16)

// ---------------- helpers ----------------
__device__ __forceinline__ uint32_t smem_u32(const void* p) {
    uint32_t a;
    asm("{ .reg .u64 t; cvta.to.shared.u64 t, %1; cvt.u32.u64 %0, t; }" : "=r"(a) : "l"(p));
    return a;
}
__device__ __forceinline__ float ex2(float x) {
    float y; asm("ex2.approx.f32 %0, %1;" : "=f"(y) : "f"(x)); return y;
}
__device__ __forceinline__ void cp_async16(uint32_t dst, const void* src) {
    asm volatile("cp.async.cg.shared.global [%0], [%1], 16;" :: "r"(dst), "l"(src) : "memory");
}
#define CP_COMMIT() asm volatile("cp.async.commit_group;" ::: "memory")
#define CP_WAIT(n)  asm volatile("cp.async.wait_group %0;" :: "n"(n) : "memory")

__device__ __forceinline__ void mma_f16(float* c, const uint32_t* a, const uint32_t* b) {
    asm volatile(
        "mma.sync.aligned.m16n8k16.row.col.f32.f16.f16.f32 "
        "{%0,%1,%2,%3}, {%4,%5,%6,%7}, {%8,%9}, {%0,%1,%2,%3};"
        : "+f"(c[0]), "+f"(c[1]), "+f"(c[2]), "+f"(c[3])
        : "r"(a[0]), "r"(a[1]), "r"(a[2]), "r"(a[3]), "r"(b[0]), "r"(b[1]));
}
__device__ __forceinline__ void ldsm_x4(uint32_t* r, uint32_t addr) {
    asm volatile("ldmatrix.sync.aligned.m8n8.x4.shared.b16 {%0,%1,%2,%3}, [%4];"
        : "=r"(r[0]), "=r"(r[1]), "=r"(r[2]), "=r"(r[3]) : "r"(addr));
}
__device__ __forceinline__ void ldsm_x2(uint32_t* r, uint32_t addr) {
    asm volatile("ldmatrix.sync.aligned.m8n8.x2.shared.b16 {%0,%1}, [%2];"
        : "=r"(r[0]), "=r"(r[1]) : "r"(addr));
}
__device__ __forceinline__ void ldsm_x2_trans(uint32_t* r, uint32_t addr) {
    asm volatile("ldmatrix.sync.aligned.m8n8.x2.trans.shared.b16 {%0,%1}, [%2];"
        : "=r"(r[0]), "=r"(r[1]) : "r"(addr));
}

// ================================================================
// Prep kernels: fp16-convert x, transpose+convert weights to [N][K]
// ================================================================
__global__ void transpose_h_kernel(const float* __restrict__ src, __half* __restrict__ dst,
                                   int R, int C) {
    __shared__ float tile[32][33];
    int bx = blockIdx.x * 32, by = blockIdx.y * 32;
    int x = bx + threadIdx.x;
    for (int i = threadIdx.y; i < 32; i += 8)
        tile[i][threadIdx.x] = src[(size_t)(by + i) * C + x];
    __syncthreads();
    int ox = by + threadIdx.x;
    for (int i = threadIdx.y; i < 32; i += 8)
        dst[(size_t)(bx + i) * R + ox] = __float2half_rn(tile[threadIdx.x][i]);
}

__global__ void conv_h_kernel(const float* __restrict__ src, __half* __restrict__ dst, int n4) {
    int i = blockIdx.x * blockDim.x + threadIdx.x;
    if (i < n4) {
        float4 v = ((const float4*)src)[i];
        ((__half2*)dst)[2 * i]     = __floats2half2_rn(v.x, v.y);
        ((__half2*)dst)[2 * i + 1] = __floats2half2_rn(v.z, v.w);
    }
}

// ================================================================
// fp16 mma GEMM: C[M,N] = A[M,K] @ Bt[N,K]^T + bias[N]
// CTA 128x128, 8 warps (warp tile 64x32), K-chunk 64 halves,
// 3-stage cp.async (register-rotated bases), ldmatrix frags, 2 CTAs/SM.
// ================================================================
#define LDT 72                                           // halves per row (64 + 8 pad)
#define STG_H (256 * LDT)                                // halves per stage
#define STG_B (STG_H * 2)                                // bytes per stage
#define GEMM_SMEM (3 * STG_B)                            // 110592 B

__global__ __launch_bounds__(256, 2) void f16_mma_gemm_kernel(
    const __half* __restrict__ A, const __half* __restrict__ Bt,
    const float* __restrict__ bias, __half* __restrict__ Ch, float* __restrict__ Cf,
    int M, int N, int K, int qcols)
{
    extern __shared__ __half smh[];
    const int tid  = threadIdx.x;
    const int lane = tid & 31;
    const int wid  = tid >> 5;
    const int wm = wid >> 2;           // 0..1  -> 64-row slab
    const int wn = wid & 3;            // 0..3  -> 32-col slab
    const int g = lane >> 2, t = lane & 3;
    const int bm = blockIdx.x * 128;
    const int bn = blockIdx.y * 128;
    const int nchunks = K >> 6;        // K / 64

    const int a_row  = (lane & 7) + ((lane >> 3) & 1) * 8;
    const int a_koff = (lane >> 4) * 8;
    const int b_row  = lane & 7;
    const int b_koff = ((lane >> 3) & 1) * 8;

    const uint32_t smb = smem_u32(smh);

    float acc[4][4][4];
    #pragma unroll
    for (int mi = 0; mi < 4; mi++)
        #pragma unroll
        for (int ni = 0; ni < 4; ni++)
            #pragma unroll
            for (int q = 0; q < 4; q++) acc[mi][ni][q] = 0.0f;

    // per-thread load offsets (constant across stages)
    const int l_r  = tid >> 3;              // 0..31
    const int l_c8 = (tid & 7) * 8;         // halves

    auto load_stage = [&](int c, uint32_t baseA) {
        const int kb = c << 6;
        const uint32_t baseB = baseA + 128u * LDT * 2u;
        #pragma unroll
        for (int i = 0; i < 8; i++) {
            int r = l_r + i * 32;           // 0..255
            if (r < 128)
                cp_async16(baseA + (uint32_t)(r * LDT + l_c8) * 2u,
                           A + (size_t)(bm + r) * K + kb + l_c8);
            else
                cp_async16(baseB + (uint32_t)((r - 128) * LDT + l_c8) * 2u,
                           Bt + (size_t)(bn + r - 128) * K + kb + l_c8);
        }
        CP_COMMIT();
    };

    uint32_t sb0 = smb, sb1 = smb + STG_B, sb2 = smb + 2u * STG_B;

    load_stage(0, sb0);
    if (nchunks > 1) load_stage(1, sb1);

    for (int c = 0; c < nchunks; c++) {
        if (c + 1 < nchunks) { CP_WAIT(1); } else { CP_WAIT(0); }
        __syncthreads();

        if (c + 2 < nchunks) load_stage(c + 2, sb2);

        const uint32_t sAu = sb0;
        const uint32_t sBu = sb0 + 128u * LDT * 2u;
        #pragma unroll
        for (int ks = 0; ks < 4; ks++) {
            const int kb = ks * 16;
            uint32_t af[4][4], bf[4][2];
            #pragma unroll
            for (int mi = 0; mi < 4; mi++)
                ldsm_x4(af[mi],
                    sAu + (uint32_t)(((wm * 64 + mi * 16 + a_row) * LDT) + kb + a_koff) * 2u);
            #pragma unroll
            for (int ni = 0; ni < 4; ni++)
                ldsm_x2(bf[ni],
                    sBu + (uint32_t)(((wn * 32 + ni * 8 + b_row) * LDT) + kb + b_koff) * 2u);
            #pragma unroll
            for (int mi = 0; mi < 4; mi++)
                #pragma unroll
                for (int ni = 0; ni < 4; ni++)
                    mma_f16(acc[mi][ni], af[mi], bf[ni]);
        }
        // rotate stage bases
        uint32_t tmp = sb0; sb0 = sb1; sb1 = sb2; sb2 = tmp;
    }
    __syncthreads();

    // ---- epilogue ----
    #pragma unroll
    for (int mi = 0; mi < 4; mi++) {
        const int r0 = bm + wm * 64 + mi * 16 + g;
        #pragma unroll
        for (int ni = 0; ni < 4; ni++) {
            const int n = bn + wn * 32 + ni * 8 + t * 2;
            const float sc = (n < qcols) ? QSC : 1.0f;
            float2 bv = *(const float2*)(bias + n);
            float v0 = (acc[mi][ni][0] + bv.x) * sc;
            float v1 = (acc[mi][ni][1] + bv.y) * sc;
            float v2 = (acc[mi][ni][2] + bv.x) * sc;
            float v3 = (acc[mi][ni][3] + bv.y) * sc;
            if (Ch) {
                *(__half2*)(Ch + (size_t)r0 * N + n)       = __floats2half2_rn(v0, v1);
                *(__half2*)(Ch + (size_t)(r0 + 8) * N + n) = __floats2half2_rn(v2, v3);
            } else {
                *(float2*)(Cf + (size_t)r0 * N + n)       = make_float2(v0, v1);
                *(float2*)(Cf + (size_t)(r0 + 8) * N + n) = make_float2(v2, v3);
            }
        }
    }
}

// ================================================================
// Flash attention, fp16 mma, DOUBLE-BUFFERED K/V across j-tiles.
// CTA 256 thr / 8 warps; tile 128q x 128kv; dh = 128; 1 CTA/SM.
// smem: Q + 2x(K/P) + 2x V + reductions = 178176 B.
// ================================================================
#define LDH 136                                         // halves per row
#define FL_TILE (128 * LDH * 2)                         // 34816 B
#define FLB_Q   0
#define FLB_KP0 (FL_TILE)
#define FLB_KP1 (2 * FL_TILE)
#define FLB_V0  (3 * FL_TILE)
#define FLB_V1  (4 * FL_TILE)
#define FLB_RM  (5 * FL_TILE)
#define FLB_RS  (FLB_RM + 2048)
#define FLASH_SMEM (FLB_RS + 2048)                      // 178176 B

__global__ __launch_bounds__(256, 1) void flash_f16_kernel(
    const __half* __restrict__ qkv, __half* __restrict__ attn_out)
{
    extern __shared__ char smc[];
    __half* Qh   = (__half*)(smc + FLB_Q);
    float* red_m = (float*)(smc + FLB_RM);
    float* red_s = (float*)(smc + FLB_RS);

    const int qt  = (int)gridDim.x - 1 - (int)blockIdx.x;   // heavy first
    const int h   = blockIdx.y;
    const int b   = blockIdx.z;
    const int tid  = threadIdx.x;
    const int lane = tid & 31;
    const int wid  = tid >> 5;
    const int wm = wid >> 2, wn = wid & 3;
    const int g = lane >> 2, t = lane & 3;

    const int a_row  = (lane & 7) + ((lane >> 3) & 1) * 8;
    const int a_koff = (lane >> 4) * 8;
    const int b_row  = lane & 7;
    const int b_koff = ((lane >> 3) & 1) * 8;
    const int v_row  = (lane & 7) + ((lane >> 3) & 1) * 8;

    const uint32_t smb = smem_u32(smc);
    const uint32_t Qu  = smb + FLB_Q;
    const uint32_t KPu0 = smb + FLB_KP0, KPu1 = smb + FLB_KP1;
    const uint32_t Vu0  = smb + FLB_V0,  Vu1  = smb + FLB_V1;

    // per-thread load offsets
    const int l_r  = tid >> 4;               // 0..15 (x8 iters -> 0..127)
    const int l_c8 = (tid & 15) * 8;

    // ---- Q tile load (group 1) ----
    const __half* qbase = qkv + (size_t)(b * SEQL + qt * 128) * D3 + h * DHEAD;
    #pragma unroll
    for (int i = 0; i < 8; i++) {
        int r = l_r + i * 16;
        cp_async16(Qu + (uint32_t)(r * LDH + l_c8) * 2u, qbase + (size_t)r * D3 + l_c8);
    }
    CP_COMMIT();

    // ---- K0 / V0 loads (groups 2, 3) ----
    {
        const __half* kbase = qkv + (size_t)(b * SEQL) * D3 + DEMB + h * DHEAD;
        #pragma unroll
        for (int i = 0; i < 8; i++) {
            int r = l_r + i * 16;
            cp_async16(KPu0 + (uint32_t)(r * LDH + l_c8) * 2u, kbase + (size_t)r * D3 + l_c8);
        }
        CP_COMMIT();
        #pragma unroll
        for (int i = 0; i < 8; i++) {
            int r = l_r + i * 16;
            cp_async16(Vu0 + (uint32_t)(r * LDH + l_c8) * 2u,
                       kbase + DEMB + (size_t)r * D3 + l_c8);
        }
        CP_COMMIT();
    }

    float o[4][4][4];
    #pragma unroll
    for (int mi = 0; mi < 4; mi++)
        #pragma unroll
        for (int ni = 0; ni < 4; ni++)
            #pragma unroll
            for (int q = 0; q < 4; q++) o[mi][ni][q] = 0.0f;
    float mrow[4][2], lrow[4][2];
    #pragma unroll
    for (int mi = 0; mi < 4; mi++) {
        mrow[mi][0] = NEGINF; mrow[mi][1] = NEGINF;
        lrow[mi][0] = 0.0f;   lrow[mi][1] = 0.0f;
    }

    for (int jt = 0; jt <= qt; jt++) {
        const int p = jt & 1;
        const uint32_t KPcur = p ? KPu1 : KPu0;
        const uint32_t Vcur  = p ? Vu1  : Vu0;
        __half* KPcp = (__half*)(smc + (p ? FLB_KP1 : FLB_KP0));

        // ---- prefetch next K/V into alternate buffers, then wait current ----
        if (jt < qt) {
            const uint32_t KPnxt = p ? KPu0 : KPu1;
            const uint32_t Vnxt  = p ? Vu0  : Vu1;
            const __half* kbn = qkv + (size_t)(b * SEQL + (jt + 1) * 128) * D3 + DEMB + h * DHEAD;
            #pragma unroll
            for (int i = 0; i < 8; i++) {
                int r = l_r + i * 16;
                cp_async16(KPnxt + (uint32_t)(r * LDH + l_c8) * 2u, kbn + (size_t)r * D3 + l_c8);
            }
            CP_COMMIT();
            #pragma unroll
            for (int i = 0; i < 8; i++) {
                int r = l_r + i * 16;
                cp_async16(Vnxt + (uint32_t)(r * LDH + l_c8) * 2u,
                           kbn + DEMB + (size_t)r * D3 + l_c8);
            }
            CP_COMMIT();
            CP_WAIT(2);          // current K/V (+Q on first iter) complete
        } else {
            CP_WAIT(0);
        }
        __syncthreads();

        // ---- S = Q @ K^T ----
        float s[4][4][4];
        #pragma unroll
        for (int mi = 0; mi < 4; mi++)
            #pragma unroll
            for (int ni = 0; ni < 4; ni++)
                #pragma unroll
                for (int q = 0; q < 4; q++) s[mi][ni][q] = 0.0f;

        #pragma unroll
        for (int ks = 0; ks < 8; ks++) {
            const int kb = ks * 16;
            uint32_t af[4][4], bf[4][2];
            #pragma unroll
            for (int mi = 0; mi < 4; mi++)
                ldsm_x4(af[mi],
                    Qu + (uint32_t)(((wm * 64 + mi * 16 + a_row) * LDH) + kb + a_koff) * 2u);
            #pragma unroll
            for (int ni = 0; ni < 4; ni++)
                ldsm_x2(bf[ni],
                    KPcur + (uint32_t)(((wn * 32 + ni * 8 + b_row) * LDH) + kb + b_koff) * 2u);
            #pragma unroll
            for (int mi = 0; mi < 4; mi++)
                #pragma unroll
                for (int ni = 0; ni < 4; ni++)
                    mma_f16(s[mi][ni], af[mi], bf[ni]);
        }

        // ---- causal mask on diagonal tile ----
        if (jt == qt) {
            #pragma unroll
            for (int mi = 0; mi < 4; mi++) {
                const int r0 = wm * 64 + mi * 16 + g;
                #pragma unroll
                for (int ni = 0; ni < 4; ni++) {
                    const int c = wn * 32 + ni * 8 + 2 * t;
                    if (c     > r0)     s[mi][ni][0] = NEGINF;
                    if (c + 1 > r0)     s[mi][ni][1] = NEGINF;
                    if (c     > r0 + 8) s[mi][ni][2] = NEGINF;
                    if (c + 1 > r0 + 8) s[mi][ni][3] = NEGINF;
                }
            }
        }

        // ---- row max ----
        float mt[4][2];
        #pragma unroll
        for (int mi = 0; mi < 4; mi++) {
            float a = fmaxf(s[mi][0][0], s[mi][0][1]);
            float bq = fmaxf(s[mi][0][2], s[mi][0][3]);
            #pragma unroll
            for (int ni = 1; ni < 4; ni++) {
                a  = fmaxf(a,  fmaxf(s[mi][ni][0], s[mi][ni][1]));
                bq = fmaxf(bq, fmaxf(s[mi][ni][2], s[mi][ni][3]));
            }
            mt[mi][0] = a; mt[mi][1] = bq;
        }
        #pragma unroll
        for (int off = 1; off <= 2; off <<= 1) {
            #pragma unroll
            for (int mi = 0; mi < 4; mi++) {
                mt[mi][0] = fmaxf(mt[mi][0], __shfl_xor_sync(0xffffffffu, mt[mi][0], off));
                mt[mi][1] = fmaxf(mt[mi][1], __shfl_xor_sync(0xffffffffu, mt[mi][1], off));
            }
        }
        if (t == 0) {
            #pragma unroll
            for (int mi = 0; mi < 4; mi++) {
                red_m[wn * 128 + wm * 64 + mi * 16 + g]     = mt[mi][0];
                red_m[wn * 128 + wm * 64 + mi * 16 + g + 8] = mt[mi][1];
            }
        }
        __syncthreads();

        float mnew[4][2], fsc[4][2];
        #pragma unroll
        for (int mi = 0; mi < 4; mi++) {
            #pragma unroll
            for (int hh = 0; hh < 2; hh++) {
                const int row = wm * 64 + mi * 16 + g + 8 * hh;
                float v = fmaxf(fmaxf(red_m[row], red_m[128 + row]),
                                fmaxf(red_m[256 + row], red_m[384 + row]));
                float mn = fmaxf(mrow[mi][hh], v);
                fsc[mi][hh]  = ex2(mrow[mi][hh] - mn);
                mnew[mi][hh] = mn;
                mrow[mi][hh] = mn;
            }
        }

        // ---- exp + row sums ----
        float rs[4][2];
        #pragma unroll
        for (int mi = 0; mi < 4; mi++) { rs[mi][0] = 0.0f; rs[mi][1] = 0.0f; }
        #pragma unroll
        for (int mi = 0; mi < 4; mi++) {
            #pragma unroll
            for (int ni = 0; ni < 4; ni++) {
                s[mi][ni][0] = ex2(s[mi][ni][0] - mnew[mi][0]);
                s[mi][ni][1] = ex2(s[mi][ni][1] - mnew[mi][0]);
                s[mi][ni][2] = ex2(s[mi][ni][2] - mnew[mi][1]);
                s[mi][ni][3] = ex2(s[mi][ni][3] - mnew[mi][1]);
                rs[mi][0] += s[mi][ni][0] + s[mi][ni][1];
                rs[mi][1] += s[mi][ni][2] + s[mi][ni][3];
            }
        }
        #pragma unroll
        for (int off = 1; off <= 2; off <<= 1) {
            #pragma unroll
            for (int mi = 0; mi < 4; mi++) {
                rs[mi][0] += __shfl_xor_sync(0xffffffffu, rs[mi][0], off);
                rs[mi][1] += __shfl_xor_sync(0xffffffffu, rs[mi][1], off);
            }
        }
        if (t == 0) {
            #pragma unroll
            for (int mi = 0; mi < 4; mi++) {
                red_s[wn * 128 + wm * 64 + mi * 16 + g]     = rs[mi][0];
                red_s[wn * 128 + wm * 64 + mi * 16 + g + 8] = rs[mi][1];
            }
        }

        // ---- P (fp16) -> current K buffer (K reads done before red_m sync) ----
        #pragma unroll
        for (int mi = 0; mi < 4; mi++) {
            const int r0 = wm * 64 + mi * 16 + g;
            #pragma unroll
            for (int ni = 0; ni < 4; ni++) {
                const int c = wn * 32 + ni * 8 + 2 * t;
                *(__half2*)&KPcp[r0 * LDH + c] =
                    __floats2half2_rn(s[mi][ni][0], s[mi][ni][1]);
                *(__half2*)&KPcp[(r0 + 8) * LDH + c] =
                    __floats2half2_rn(s[mi][ni][2], s[mi][ni][3]);
            }
        }
        __syncthreads();       // P + red_s visible (V already waited at top)

        // ---- l update, O rescale ----
        #pragma unroll
        for (int mi = 0; mi < 4; mi++) {
            #pragma unroll
            for (int hh = 0; hh < 2; hh++) {
                const int row = wm * 64 + mi * 16 + g + 8 * hh;
                float sum = red_s[row] + red_s[128 + row] + red_s[256 + row] + red_s[384 + row];
                lrow[mi][hh] = lrow[mi][hh] * fsc[mi][hh] + sum;
            }
            #pragma unroll
            for (int ni = 0; ni < 4; ni++) {
                o[mi][ni][0] *= fsc[mi][0];
                o[mi][ni][1] *= fsc[mi][0];
                o[mi][ni][2] *= fsc[mi][1];
                o[mi][ni][3] *= fsc[mi][1];
            }
        }

        // ---- O += P @ V ----
        #pragma unroll
        for (int ks = 0; ks < 8; ks++) {
            const int kb = ks * 16;
            uint32_t af[4][4], bf[4][2];
            #pragma unroll
            for (int mi = 0; mi < 4; mi++)
                ldsm_x4(af[mi],
                    KPcur + (uint32_t)(((wm * 64 + mi * 16 + a_row) * LDH) + kb + a_koff) * 2u);
            #pragma unroll
            for (int ni = 0; ni < 4; ni++)
                ldsm_x2_trans(bf[ni],
                    Vcur + (uint32_t)(((kb + v_row) * LDH) + wn * 32 + ni * 8) * 2u);
            #pragma unroll
            for (int mi = 0; mi < 4; mi++)
                #pragma unroll
                for (int ni = 0; ni < 4; ni++)
                    mma_f16(o[mi][ni], af[mi], bf[ni]);
        }
        __syncthreads();       // buf p fully consumed before iter jt+1 refills it
    }

    // ---- epilogue: O /= l, fp16 out (feeds GEMM2) ----
    const size_t orow = (size_t)(b * SEQL + qt * 128);
    #pragma unroll
    for (int mi = 0; mi < 4; mi++) {
        const float i0 = 1.0f / lrow[mi][0];
        const float i1 = 1.0f / lrow[mi][1];
        const int r0 = wm * 64 + mi * 16 + g;
        #pragma unroll
        for (int ni = 0; ni < 4; ni++) {
            const int cc = h * DHEAD + wn * 32 + ni * 8 + 2 * t;
            *(__half2*)(attn_out + (orow + r0) * DEMB + cc) =
                __floats2half2_rn(o[mi][ni][0] * i0, o[mi][ni][1] * i0);
            *(__half2*)(attn_out + (orow + r0 + 8) * DEMB + cc) =
                __floats2half2_rn(o[mi][ni][2] * i1, o[mi][ni][3] * i1);
        }
    }
}

// ================================================================
// Launcher
// ================================================================
extern "C" void kernel_launch(void* const* d_in, const int* in_sizes, int n_in,
                              void* d_out, int out_size)
{
    (void)in_sizes; (void)n_in; (void)out_size;
    const float* x     = (const float*)d_in[0];
    const float* w_in  = (const float*)d_in[1];
    const float* b_in  = (const float*)d_in[2];
    const float* w_out = (const float*)d_in[3];
    const float* b_out = (const float*)d_in[4];
    float* out = (float*)d_out;

    void *qkv_p, *attn_p, *xh_p, *wT1_p, *wT2_p;
    cudaGetSymbolAddress(&qkv_p,  g_qkv);
    cudaGetSymbolAddress(&attn_p, g_attn);
    cudaGetSymbolAddress(&xh_p,   g_xh);
    cudaGetSymbolAddress(&wT1_p,  g_wT1);
    cudaGetSymbolAddress(&wT2_p,  g_wT2);

    cudaFuncSetAttribute(flash_f16_kernel,
                         cudaFuncAttributeMaxDynamicSharedMemorySize, FLASH_SMEM);
    cudaFuncSetAttribute(f16_mma_gemm_kernel,
                         cudaFuncAttributeMaxDynamicSharedMemorySize, GEMM_SMEM);

    // prep: wT1 = h(w_in^T), wT2 = h(w_out^T), xh = h(x)
    transpose_h_kernel<<<dim3(D3 / 32, DEMB / 32), dim3(32, 8)>>>(w_in, (__half*)wT1_p, DEMB, D3);
    transpose_h_kernel<<<dim3(DEMB / 32, DEMB / 32), dim3(32, 8)>>>(w_out, (__half*)wT2_p, DEMB, DEMB);
    conv_h_kernel<<<(NTOK * DEMB / 4 + 255) / 256, 256>>>(x, (__half*)xh_p, NTOK * DEMB / 4);

    // 1) qkv = x @ w_in + b_in  (fp16 out; Q cols pre-scaled by QSC)
    f16_mma_gemm_kernel<<<dim3(NTOK / 128, D3 / 128), 256, GEMM_SMEM>>>(
        (const __half*)xh_p, (const __half*)wT1_p, b_in,
        (__half*)qkv_p, nullptr, NTOK, D3, DEMB, DEMB);

    // 2) causal flash attention (fp16 mma, double-buffered K/V) -> g_attn
    flash_f16_kernel<<<dim3(SEQL / 128, NHEADS, BATCH), 256, FLASH_SMEM>>>(
        (const __half*)qkv_p, (__half*)attn_p);

    // 3) out = attn @ w_out + b_out  (fp32 out)
    f16_mma_gemm_kernel<<<dim3(NTOK / 128, DEMB / 128), 256, GEMM_SMEM>>>(
        (const __half*)attn_p, (const __half*)wT2_p, b_out,
        nullptr, out, NTOK, DEMB, DEMB, 0);
}

// round 10
// speedup vs baseline: 2.1957x; 1.0350x over previous
#include <cuda_runtime.h>
#include <cuda_fp16.h>
#include <math.h>
#include <stdint.h>

#define BATCH   2
#define SEQL    2048
#define DEMB    2048
#define NHEADS  16
#define DHEAD   128
#define NTOK    (BATCH * SEQL)       // 4096
#define D3      (3 * DEMB)           // 6144

// combined score scale: log2(e)/sqrt(128), folded into Q at GEMM1 epilogue
#define QSC 0.1275174446f
#define NEGINF __int_as_float(0xff800000)

// -------- scratch (__device__ globals; no allocs allowed) --------
__device__ __half g_qkv [(size_t)NTOK * D3];     // 48 MB (fp16, Q pre-scaled)
__device__ __half g_attn[(size_t)NTOK * DEMB];   // 16 MB
__device__ __half g_xh  [(size_t)NTOK * DEMB];   // 16 MB (fp16 x)
__device__ __half g_wT1 [(size_t)D3   * DEMB];   // 24 MB (w_in^T fp16)
__device__ __half g_wT2 [(size_t)DEMB * DEMB];   //  8 MB (w_out^T fp16)

// ---------------- helpers ----------------
__device__ __forceinline__ uint32_t smem_u32(const void* p) {
    uint32_t a;
    asm("{ .reg .u64 t; cvta.to.shared.u64 t, %1; cvt.u32.u64 %0, t; }" : "=r"(a) : "l"(p));
    return a;
}
__device__ __forceinline__ float ex2(float x) {
    float y; asm("ex2.approx.f32 %0, %1;" : "=f"(y) : "f"(x)); return y;
}
__device__ __forceinline__ void cp_async16(uint32_t dst, const void* src) {
    asm volatile("cp.async.cg.shared.global [%0], [%1], 16;" :: "r"(dst), "l"(src) : "memory");
}
#define CP_COMMIT() asm volatile("cp.async.commit_group;" ::: "memory")
#define CP_WAIT(n)  asm volatile("cp.async.wait_group %0;" :: "n"(n) : "memory")

__device__ __forceinline__ void mma_f16(float* c, const uint32_t* a, const uint32_t* b) {
    asm volatile(
        "mma.sync.aligned.m16n8k16.row.col.f32.f16.f16.f32 "
        "{%0,%1,%2,%3}, {%4,%5,%6,%7}, {%8,%9}, {%0,%1,%2,%3};"
        : "+f"(c[0]), "+f"(c[1]), "+f"(c[2]), "+f"(c[3])
        : "r"(a[0]), "r"(a[1]), "r"(a[2]), "r"(a[3]), "r"(b[0]), "r"(b[1]));
}
__device__ __forceinline__ void ldsm_x4(uint32_t* r, uint32_t addr) {
    asm volatile("ldmatrix.sync.aligned.m8n8.x4.shared.b16 {%0,%1,%2,%3}, [%4];"
        : "=r"(r[0]), "=r"(r[1]), "=r"(r[2]), "=r"(r[3]) : "r"(addr));
}
__device__ __forceinline__ void ldsm_x2(uint32_t* r, uint32_t addr) {
    asm volatile("ldmatrix.sync.aligned.m8n8.x2.shared.b16 {%0,%1}, [%2];"
        : "=r"(r[0]), "=r"(r[1]) : "r"(addr));
}
__device__ __forceinline__ void ldsm_x4_trans(uint32_t* r, uint32_t addr) {
    asm volatile("ldmatrix.sync.aligned.m8n8.x4.trans.shared.b16 {%0,%1,%2,%3}, [%4];"
        : "=r"(r[0]), "=r"(r[1]), "=r"(r[2]), "=r"(r[3]) : "r"(addr));
}
__device__ __forceinline__ uint32_t packh2(float lo, float hi) {
    __half2 h = __floats2half2_rn(lo, hi);
    return *(uint32_t*)&h;
}

// ================================================================
// Prep kernels: fp16-convert x, transpose+convert weights to [N][K]
// ================================================================
__global__ void transpose_h_kernel(const float* __restrict__ src, __half* __restrict__ dst,
                                   int R, int C) {
    __shared__ float tile[32][33];
    int bx = blockIdx.x * 32, by = blockIdx.y * 32;
    int x = bx + threadIdx.x;
    for (int i = threadIdx.y; i < 32; i += 8)
        tile[i][threadIdx.x] = src[(size_t)(by + i) * C + x];
    __syncthreads();
    int ox = by + threadIdx.x;
    for (int i = threadIdx.y; i < 32; i += 8)
        dst[(size_t)(bx + i) * R + ox] = __float2half_rn(tile[threadIdx.x][i]);
}

__global__ void conv_h_kernel(const float* __restrict__ src, __half* __restrict__ dst, int n4) {
    int i = blockIdx.x * blockDim.x + threadIdx.x;
    if (i < n4) {
        float4 v = ((const float4*)src)[i];
        ((__half2*)dst)[2 * i]     = __floats2half2_rn(v.x, v.y);
        ((__half2*)dst)[2 * i + 1] = __floats2half2_rn(v.z, v.w);
    }
}

// ================================================================
// fp16 mma GEMM (unchanged from R9): CTA 128x128, warp 64x32,
// K-chunk 64, 3-stage cp.async, ldmatrix, 2 CTAs/SM.
// ================================================================
#define LDT 72
#define STG_H (256 * LDT)
#define STG_B (STG_H * 2)
#define GEMM_SMEM (3 * STG_B)                            // 110592 B

__global__ __launch_bounds__(256, 2) void f16_mma_gemm_kernel(
    const __half* __restrict__ A, const __half* __restrict__ Bt,
    const float* __restrict__ bias, __half* __restrict__ Ch, float* __restrict__ Cf,
    int M, int N, int K, int qcols)
{
    extern __shared__ __half smh[];
    const int tid  = threadIdx.x;
    const int lane = tid & 31;
    const int wid  = tid >> 5;
    const int wm = wid >> 2;
    const int wn = wid & 3;
    const int g = lane >> 2, t = lane & 3;
    const int bm = blockIdx.x * 128;
    const int bn = blockIdx.y * 128;
    const int nchunks = K >> 6;

    const int a_row  = (lane & 7) + ((lane >> 3) & 1) * 8;
    const int a_koff = (lane >> 4) * 8;
    const int b_row  = lane & 7;
    const int b_koff = ((lane >> 3) & 1) * 8;

    const uint32_t smb = smem_u32(smh);

    float acc[4][4][4];
    #pragma unroll
    for (int mi = 0; mi < 4; mi++)
        #pragma unroll
        for (int ni = 0; ni < 4; ni++)
            #pragma unroll
            for (int q = 0; q < 4; q++) acc[mi][ni][q] = 0.0f;

    const int l_r  = tid >> 3;
    const int l_c8 = (tid & 7) * 8;

    auto load_stage = [&](int c, uint32_t baseA) {
        const int kb = c << 6;
        const uint32_t baseB = baseA + 128u * LDT * 2u;
        #pragma unroll
        for (int i = 0; i < 8; i++) {
            int r = l_r + i * 32;
            if (r < 128)
                cp_async16(baseA + (uint32_t)(r * LDT + l_c8) * 2u,
                           A + (size_t)(bm + r) * K + kb + l_c8);
            else
                cp_async16(baseB + (uint32_t)((r - 128) * LDT + l_c8) * 2u,
                           Bt + (size_t)(bn + r - 128) * K + kb + l_c8);
        }
        CP_COMMIT();
    };

    uint32_t sb0 = smb, sb1 = smb + STG_B, sb2 = smb + 2u * STG_B;

    load_stage(0, sb0);
    if (nchunks > 1) load_stage(1, sb1);

    for (int c = 0; c < nchunks; c++) {
        if (c + 1 < nchunks) { CP_WAIT(1); } else { CP_WAIT(0); }
        __syncthreads();

        if (c + 2 < nchunks) load_stage(c + 2, sb2);

        const uint32_t sAu = sb0;
        const uint32_t sBu = sb0 + 128u * LDT * 2u;
        #pragma unroll
        for (int ks = 0; ks < 4; ks++) {
            const int kb = ks * 16;
            uint32_t af[4][4], bf[4][2];
            #pragma unroll
            for (int mi = 0; mi < 4; mi++)
                ldsm_x4(af[mi],
                    sAu + (uint32_t)(((wm * 64 + mi * 16 + a_row) * LDT) + kb + a_koff) * 2u);
            #pragma unroll
            for (int ni = 0; ni < 4; ni++)
                ldsm_x2(bf[ni],
                    sBu + (uint32_t)(((wn * 32 + ni * 8 + b_row) * LDT) + kb + b_koff) * 2u);
            #pragma unroll
            for (int mi = 0; mi < 4; mi++)
                #pragma unroll
                for (int ni = 0; ni < 4; ni++)
                    mma_f16(acc[mi][ni], af[mi], bf[ni]);
        }
        uint32_t tmp = sb0; sb0 = sb1; sb1 = sb2; sb2 = tmp;
    }
    __syncthreads();

    #pragma unroll
    for (int mi = 0; mi < 4; mi++) {
        const int r0 = bm + wm * 64 + mi * 16 + g;
        #pragma unroll
        for (int ni = 0; ni < 4; ni++) {
            const int n = bn + wn * 32 + ni * 8 + t * 2;
            const float sc = (n < qcols) ? QSC : 1.0f;
            float2 bv = *(const float2*)(bias + n);
            float v0 = (acc[mi][ni][0] + bv.x) * sc;
            float v1 = (acc[mi][ni][1] + bv.y) * sc;
            float v2 = (acc[mi][ni][2] + bv.x) * sc;
            float v3 = (acc[mi][ni][3] + bv.y) * sc;
            if (Ch) {
                *(__half2*)(Ch + (size_t)r0 * N + n)       = __floats2half2_rn(v0, v1);
                *(__half2*)(Ch + (size_t)(r0 + 8) * N + n) = __floats2half2_rn(v2, v3);
            } else {
                *(float2*)(Cf + (size_t)r0 * N + n)       = make_float2(v0, v1);
                *(float2*)(Cf + (size_t)(r0 + 8) * N + n) = make_float2(v2, v3);
            }
        }
    }
}

// ================================================================
// Flash attention, FA2-style: warp owns 16 q-rows x full kv/dh.
// Softmax warp-local (quad shfl); P register-resident into PV mma.
// Double-buffered K/V. 1 CTA/SM; smem = 5 tiles = 174080 B.
// ================================================================
#define LDH 136
#define FL_TILE (128 * LDH * 2)                         // 34816 B
#define FLB_Q   0
#define FLB_K0  (FL_TILE)
#define FLB_K1  (2 * FL_TILE)
#define FLB_V0  (3 * FL_TILE)
#define FLB_V1  (4 * FL_TILE)
#define FLASH_SMEM (5 * FL_TILE)                        // 174080 B

__global__ __launch_bounds__(256, 1) void flash_f16_kernel(
    const __half* __restrict__ qkv, __half* __restrict__ attn_out)
{
    extern __shared__ char smc[];

    const int qt  = (int)gridDim.x - 1 - (int)blockIdx.x;   // heavy first
    const int h   = blockIdx.y;
    const int b   = blockIdx.z;
    const int tid  = threadIdx.x;
    const int lane = tid & 31;
    const int wid  = tid >> 5;
    const int g = lane >> 2, t = lane & 3;

    // A-frag (Q) ldsm.x4 address components
    const int a_row  = (lane & 7) + ((lane >> 3) & 1) * 8;
    const int a_koff = (lane >> 4) * 8;
    // K B-frag pair ldsm.x4: lanes 0-7 (n,k0) 8-15 (n,k8) 16-23 (n+8,k0) 24-31 (n+8,k8)
    const int kb_row  = (lane & 7) + ((lane >> 4) & 1) * 8;   // + nj*16
    const int kb_koff = ((lane >> 3) & 1) * 8;                // + kb
    // V B-frag pair ldsm.x4.trans: rows = k, cols = n
    const int vb_row  = (lane & 7) + ((lane >> 3) & 1) * 8;   // + kb
    const int vb_coff = ((lane >> 4) & 1) * 8;                // + nj*16

    const uint32_t smb = smem_u32(smc);
    const uint32_t Qu  = smb + FLB_Q;
    const uint32_t Ku0 = smb + FLB_K0, Ku1 = smb + FLB_K1;
    const uint32_t Vu0 = smb + FLB_V0, Vu1 = smb + FLB_V1;

    const int l_r  = tid >> 4;               // 0..15
    const int l_c8 = (tid & 15) * 8;

    // ---- Q tile load (group 1) ----
    const __half* qbase = qkv + (size_t)(b * SEQL + qt * 128) * D3 + h * DHEAD;
    #pragma unroll
    for (int i = 0; i < 8; i++) {
        int r = l_r + i * 16;
        cp_async16(Qu + (uint32_t)(r * LDH + l_c8) * 2u, qbase + (size_t)r * D3 + l_c8);
    }
    CP_COMMIT();

    // ---- K0 / V0 loads (groups 2, 3) ----
    {
        const __half* kbase = qkv + (size_t)(b * SEQL) * D3 + DEMB + h * DHEAD;
        #pragma unroll
        for (int i = 0; i < 8; i++) {
            int r = l_r + i * 16;
            cp_async16(Ku0 + (uint32_t)(r * LDH + l_c8) * 2u, kbase + (size_t)r * D3 + l_c8);
        }
        CP_COMMIT();
        #pragma unroll
        for (int i = 0; i < 8; i++) {
            int r = l_r + i * 16;
            cp_async16(Vu0 + (uint32_t)(r * LDH + l_c8) * 2u,
                       kbase + DEMB + (size_t)r * D3 + l_c8);
        }
        CP_COMMIT();
    }

    float o[16][4];
    #pragma unroll
    for (int ni = 0; ni < 16; ni++)
        #pragma unroll
        for (int q = 0; q < 4; q++) o[ni][q] = 0.0f;
    float mrow0 = NEGINF, mrow1 = NEGINF, lrow0 = 0.0f, lrow1 = 0.0f;

    for (int jt = 0; jt <= qt; jt++) {
        const int p = jt & 1;
        const uint32_t Kcur = p ? Ku1 : Ku0;
        const uint32_t Vcur = p ? Vu1 : Vu0;

        // ---- prefetch next K/V into alternate buffers, then wait current ----
        if (jt < qt) {
            const uint32_t Knxt = p ? Ku0 : Ku1;
            const uint32_t Vnxt = p ? Vu0 : Vu1;
            const __half* kbn = qkv + (size_t)(b * SEQL + (jt + 1) * 128) * D3 + DEMB + h * DHEAD;
            #pragma unroll
            for (int i = 0; i < 8; i++) {
                int r = l_r + i * 16;
                cp_async16(Knxt + (uint32_t)(r * LDH + l_c8) * 2u, kbn + (size_t)r * D3 + l_c8);
            }
            CP_COMMIT();
            #pragma unroll
            for (int i = 0; i < 8; i++) {
                int r = l_r + i * 16;
                cp_async16(Vnxt + (uint32_t)(r * LDH + l_c8) * 2u,
                           kbn + DEMB + (size_t)r * D3 + l_c8);
            }
            CP_COMMIT();
            CP_WAIT(2);
        } else {
            CP_WAIT(0);
        }
        __syncthreads();

        // ---- S = Q @ K^T : warp computes 16 rows x 128 kv ----
        float s[16][4];
        #pragma unroll
        for (int ni = 0; ni < 16; ni++)
            #pragma unroll
            for (int q = 0; q < 4; q++) s[ni][q] = 0.0f;

        #pragma unroll
        for (int ks = 0; ks < 8; ks++) {
            const int kb = ks * 16;
            uint32_t af[4];
            ldsm_x4(af, Qu + (uint32_t)(((wid * 16 + a_row) * LDH) + kb + a_koff) * 2u);
            #pragma unroll
            for (int nj = 0; nj < 8; nj++) {
                uint32_t r4[4];
                ldsm_x4(r4, Kcur + (uint32_t)(((nj * 16 + kb_row) * LDH) + kb + kb_koff) * 2u);
                mma_f16(s[2 * nj],     af, r4);
                mma_f16(s[2 * nj + 1], af, r4 + 2);
            }
        }

        // ---- causal mask on diagonal tile ----
        if (jt == qt) {
            const int r0 = wid * 16 + g;
            #pragma unroll
            for (int ni = 0; ni < 16; ni++) {
                const int c = ni * 8 + 2 * t;
                if (c     > r0)     s[ni][0] = NEGINF;
                if (c + 1 > r0)     s[ni][1] = NEGINF;
                if (c     > r0 + 8) s[ni][2] = NEGINF;
                if (c + 1 > r0 + 8) s[ni][3] = NEGINF;
            }
        }

        // ---- row max (thread -> quad shfl; fully warp-local) ----
        float m0 = NEGINF, m1 = NEGINF;
        #pragma unroll
        for (int ni = 0; ni < 16; ni++) {
            m0 = fmaxf(m0, fmaxf(s[ni][0], s[ni][1]));
            m1 = fmaxf(m1, fmaxf(s[ni][2], s[ni][3]));
        }
        #pragma unroll
        for (int off = 1; off <= 2; off <<= 1) {
            m0 = fmaxf(m0, __shfl_xor_sync(0xffffffffu, m0, off));
            m1 = fmaxf(m1, __shfl_xor_sync(0xffffffffu, m1, off));
        }
        const float mn0 = fmaxf(mrow0, m0);
        const float mn1 = fmaxf(mrow1, m1);
        const float fsc0 = ex2(mrow0 - mn0);   // 0 on first tile
        const float fsc1 = ex2(mrow1 - mn1);
        mrow0 = mn0; mrow1 = mn1;

        // ---- exp + row sums ----
        float rs0 = 0.0f, rs1 = 0.0f;
        #pragma unroll
        for (int ni = 0; ni < 16; ni++) {
            s[ni][0] = ex2(s[ni][0] - mn0);
            s[ni][1] = ex2(s[ni][1] - mn0);
            s[ni][2] = ex2(s[ni][2] - mn1);
            s[ni][3] = ex2(s[ni][3] - mn1);
            rs0 += s[ni][0] + s[ni][1];
            rs1 += s[ni][2] + s[ni][3];
        }
        #pragma unroll
        for (int off = 1; off <= 2; off <<= 1) {
            rs0 += __shfl_xor_sync(0xffffffffu, rs0, off);
            rs1 += __shfl_xor_sync(0xffffffffu, rs1, off);
        }
        lrow0 = lrow0 * fsc0 + rs0;
        lrow1 = lrow1 * fsc1 + rs1;

        // ---- O rescale ----
        #pragma unroll
        for (int ni = 0; ni < 16; ni++) {
            o[ni][0] *= fsc0; o[ni][1] *= fsc0;
            o[ni][2] *= fsc1; o[ni][3] *= fsc1;
        }

        // ---- O += P @ V : P direct from registers ----
        #pragma unroll
        for (int ks = 0; ks < 8; ks++) {
            const int kb = ks * 16;
            uint32_t af[4];
            af[0] = packh2(s[2 * ks][0],     s[2 * ks][1]);
            af[1] = packh2(s[2 * ks][2],     s[2 * ks][3]);
            af[2] = packh2(s[2 * ks + 1][0], s[2 * ks + 1][1]);
            af[3] = packh2(s[2 * ks + 1][2], s[2 * ks + 1][3]);
            #pragma unroll
            for (int nj = 0; nj < 8; nj++) {
                uint32_t r4[4];
                ldsm_x4_trans(r4,
                    Vcur + (uint32_t)(((kb + vb_row) * LDH) + nj * 16 + vb_coff) * 2u);
                mma_f16(o[2 * nj],     af, r4);
                mma_f16(o[2 * nj + 1], af, r4 + 2);
            }
        }
        __syncthreads();       // buf p fully consumed before refill
    }

    // ---- epilogue: O /= l, fp16 out (feeds GEMM2) ----
    const size_t orow = (size_t)(b * SEQL + qt * 128) + wid * 16 + g;
    const float i0 = 1.0f / lrow0;
    const float i1 = 1.0f / lrow1;
    #pragma unroll
    for (int ni = 0; ni < 16; ni++) {
        const int cc = h * DHEAD + ni * 8 + 2 * t;
        *(__half2*)(attn_out + orow * DEMB + cc) =
            __floats2half2_rn(o[ni][0] * i0, o[ni][1] * i0);
        *(__half2*)(attn_out + (orow + 8) * DEMB + cc) =
            __floats2half2_rn(o[ni][2] * i1, o[ni][3] * i1);
    }
}

// ================================================================
// Launcher
// ================================================================
extern "C" void kernel_launch(void* const* d_in, const int* in_sizes, int n_in,
                              void* d_out, int out_size)
{
    (void)in_sizes; (void)n_in; (void)out_size;
    const float* x     = (const float*)d_in[0];
    const float* w_in  = (const float*)d_in[1];
    const float* b_in  = (const float*)d_in[2];
    const float* w_out = (const float*)d_in[3];
    const float* b_out = (const float*)d_in[4];
    float* out = (float*)d_out;

    void *qkv_p, *attn_p, *xh_p, *wT1_p, *wT2_p;
    cudaGetSymbolAddress(&qkv_p,  g_qkv);
    cudaGetSymbolAddress(&attn_p, g_attn);
    cudaGetSymbolAddress(&xh_p,   g_xh);
    cudaGetSymbolAddress(&wT1_p,  g_wT1);
    cudaGetSymbolAddress(&wT2_p,  g_wT2);

    cudaFuncSetAttribute(flash_f16_kernel,
                         cudaFuncAttributeMaxDynamicSharedMemorySize, FLASH_SMEM);
    cudaFuncSetAttribute(f16_mma_gemm_kernel,
                         cudaFuncAttributeMaxDynamicSharedMemorySize, GEMM_SMEM);

    // prep: wT1 = h(w_in^T), wT2 = h(w_out^T), xh = h(x)
    transpose_h_kernel<<<dim3(D3 / 32, DEMB / 32), dim3(32, 8)>>>(w_in, (__half*)wT1_p, DEMB, D3);
    transpose_h_kernel<<<dim3(DEMB / 32, DEMB / 32), dim3(32, 8)>>>(w_out, (__half*)wT2_p, DEMB, DEMB);
    conv_h_kernel<<<(NTOK * DEMB / 4 + 255) / 256, 256>>>(x, (__half*)xh_p, NTOK * DEMB / 4);

    // 1) qkv = x @ w_in + b_in  (fp16 out; Q cols pre-scaled by QSC)
    f16_mma_gemm_kernel<<<dim3(NTOK / 128, D3 / 128), 256, GEMM_SMEM>>>(
        (const __half*)xh_p, (const __half*)wT1_p, b_in,
        (__half*)qkv_p, nullptr, NTOK, D3, DEMB, DEMB);

    // 2) causal flash attention (FA2 layout, reg-resident P) -> g_attn
    flash_f16_kernel<<<dim3(SEQL / 128, NHEADS, BATCH), 256, FLASH_SMEM>>>(
        (const __half*)qkv_p, (__half*)attn_p);

    // 3) out = attn @ w_out + b_out  (fp32 out)
    f16_mma_gemm_kernel<<<dim3(NTOK / 128, DEMB / 128), 256, GEMM_SMEM>>>(
        (const __half*)attn_p, (const __half*)wT2_p, b_out,
        nullptr, out, NTOK, DEMB, DEMB, 0);
}